// round 1
// baseline (speedup 1.0000x reference)
#include <cuda_runtime.h>
#include <math.h>
#include <stdint.h>

// Problem shape (fixed by the dataset)
#define BB   2
#define NN   1024
#define LLEN 4096
#define CDIM 1024
#define HH   16
#define DD   64
#define ATTN_SCALE 0.125f   // 64^-0.5

// Scratch (device globals — no allocation allowed in kernel_launch)
__device__ float g_Q[BB * NN * CDIM];     // 8 MB
__device__ float g_K[BB * LLEN * CDIM];   // 32 MB
__device__ float g_V[BB * LLEN * CDIM];   // 32 MB
__device__ float g_Ao[BB * NN * CDIM];    // 8 MB

// ---------------------------------------------------------------------------
// GEMM: C[m][n] = sum_k A[m][k] * B[n][k]  (+ bias[n])
// Tile 64x64, BK=16, 256 threads, 4x4 register micro-tile per thread.
// ---------------------------------------------------------------------------
__global__ __launch_bounds__(256) void gemm_abt(
    float* __restrict__ C, const float* __restrict__ A,
    const float* __restrict__ B, const float* __restrict__ bias,
    int M, int N, int K)
{
    __shared__ float As[16][64];   // [k][m]
    __shared__ float Bs[16][64];   // [k][n]

    const int m0 = blockIdx.y * 64;
    const int n0 = blockIdx.x * 64;
    const int tid = threadIdx.x;
    const int tx = tid & 15;       // 0..15 -> n micro
    const int ty = tid >> 4;       // 0..15 -> m micro

    const int lr = tid >> 2;          // 0..63: tile row for loading
    const int lk = (tid & 3) << 2;    // 0,4,8,12: k offset (float4)

    const float* Ap = A + (size_t)(m0 + lr) * K + lk;
    const float* Bp = B + (size_t)(n0 + lr) * K + lk;

    float acc[4][4] = {};

    for (int k0 = 0; k0 < K; k0 += 16) {
        float4 a = *(const float4*)(Ap + k0);
        float4 b = *(const float4*)(Bp + k0);
        As[lk + 0][lr] = a.x; As[lk + 1][lr] = a.y;
        As[lk + 2][lr] = a.z; As[lk + 3][lr] = a.w;
        Bs[lk + 0][lr] = b.x; Bs[lk + 1][lr] = b.y;
        Bs[lk + 2][lr] = b.z; Bs[lk + 3][lr] = b.w;
        __syncthreads();

#pragma unroll
        for (int k = 0; k < 16; k++) {
            float4 av = *(const float4*)&As[k][ty * 4];
            float4 bv = *(const float4*)&Bs[k][tx * 4];
            float ar[4] = {av.x, av.y, av.z, av.w};
            float br[4] = {bv.x, bv.y, bv.z, bv.w};
#pragma unroll
            for (int i = 0; i < 4; i++)
#pragma unroll
                for (int j = 0; j < 4; j++)
                    acc[i][j] += ar[i] * br[j];
        }
        __syncthreads();
    }

#pragma unroll
    for (int i = 0; i < 4; i++) {
        const int m = m0 + ty * 4 + i;
        const int n = n0 + tx * 4;
        float4 o;
        o.x = acc[i][0]; o.y = acc[i][1]; o.z = acc[i][2]; o.w = acc[i][3];
        if (bias != nullptr) {
            o.x += bias[n + 0]; o.y += bias[n + 1];
            o.z += bias[n + 2]; o.w += bias[n + 3];
        }
        *(float4*)&C[(size_t)m * N + n] = o;
    }
}

// ---------------------------------------------------------------------------
// Flash attention (fp32). One block = 64 queries of one (b,h).
// 128 threads: 16(x: cols) x 8(y: rows). Streams L in tiles of 64 keys with
// online softmax. Q/K stored transposed [d][row] in smem for outer-product GEMM.
// ---------------------------------------------------------------------------
#define QT 64
#define KT 64
#define ST_STRIDE 68   // padded stride for S/P tile [c][r]

__global__ __launch_bounds__(128) void attn_kernel(
    float* __restrict__ O, const float* __restrict__ Q,
    const float* __restrict__ K, const float* __restrict__ V)
{
    extern __shared__ float smem[];
    float* Qs  = smem;                 // [DD][QT]   (transposed)
    float* Ks  = Qs  + DD * QT;        // [DD][KT]   (transposed)
    float* Vs  = Ks  + DD * KT;        // [KT][DD]   (row-major)
    float* St  = Vs  + KT * DD;        // [KT][ST_STRIDE]  S then P, [c][r]
    float* smx = St  + KT * ST_STRIDE; // [QT] running max
    float* slv = smx + QT;             // [QT] running sum
    float* sal = slv + QT;             // [QT] rescale factor

    const int tid = threadIdx.x;
    const int tx  = tid & 15;   // 0..15
    const int ty  = tid >> 4;   // 0..7
    const int qt = blockIdx.x;
    const int h  = blockIdx.y;
    const int b  = blockIdx.z;

    const float* Qg = Q + (size_t)(b * NN + qt * QT) * CDIM + h * DD;
    const float* Kg = K + (size_t)b * LLEN * CDIM + h * DD;
    const float* Vg = V + (size_t)b * LLEN * CDIM + h * DD;

    // Load Q tile, transposed into Qs[d][r]
    for (int i = tid; i < QT * (DD / 4); i += 128) {
        const int r  = i >> 4;            // query row 0..63
        const int dq = (i & 15) << 2;     // d offset 0..60
        float4 v = *(const float4*)(Qg + (size_t)r * CDIM + dq);
        Qs[(dq + 0) * QT + r] = v.x;
        Qs[(dq + 1) * QT + r] = v.y;
        Qs[(dq + 2) * QT + r] = v.z;
        Qs[(dq + 3) * QT + r] = v.w;
    }
    if (tid < QT) { smx[tid] = -1e30f; slv[tid] = 0.0f; }

    float acc[8][4] = {};   // O[r = ty*8+i][d = tx*4+j]

    for (int kt = 0; kt < LLEN / KT; kt++) {
        __syncthreads();   // protects Qs (first iter) and Ks/Vs/St reuse

        // Load K (transposed) and V (row-major) tiles
        const float* Kt_ = Kg + (size_t)(kt * KT) * CDIM;
        const float* Vt_ = Vg + (size_t)(kt * KT) * CDIM;
        for (int i = tid; i < KT * (DD / 4); i += 128) {
            const int r  = i >> 4;
            const int dq = (i & 15) << 2;
            float4 kv = *(const float4*)(Kt_ + (size_t)r * CDIM + dq);
            Ks[(dq + 0) * KT + r] = kv.x;
            Ks[(dq + 1) * KT + r] = kv.y;
            Ks[(dq + 2) * KT + r] = kv.z;
            Ks[(dq + 3) * KT + r] = kv.w;
            float4 vv = *(const float4*)(Vt_ + (size_t)r * CDIM + dq);
            *(float4*)&Vs[r * DD + dq] = vv;
        }
        __syncthreads();

        // S = Q K^T  (scaled), written transposed St[c][r]
        float s[8][4] = {};
#pragma unroll 8
        for (int d = 0; d < DD; d++) {
            float4 q0 = *(const float4*)&Qs[d * QT + ty * 8];
            float4 q1 = *(const float4*)&Qs[d * QT + ty * 8 + 4];
            float4 kc = *(const float4*)&Ks[d * KT + tx * 4];
            float qa[8] = {q0.x, q0.y, q0.z, q0.w, q1.x, q1.y, q1.z, q1.w};
            float kb[4] = {kc.x, kc.y, kc.z, kc.w};
#pragma unroll
            for (int i = 0; i < 8; i++)
#pragma unroll
                for (int j = 0; j < 4; j++)
                    s[i][j] += qa[i] * kb[j];
        }
#pragma unroll
        for (int i = 0; i < 8; i++)
#pragma unroll
            for (int j = 0; j < 4; j++)
                St[(tx * 4 + j) * ST_STRIDE + (ty * 8 + i)] = s[i][j] * ATTN_SCALE;
        __syncthreads();

        // Online softmax: thread r owns query row r (threads 0..63)
        if (tid < QT) {
            const int r = tid;
            float tmax = -1e30f;
#pragma unroll 8
            for (int c = 0; c < KT; c++)
                tmax = fmaxf(tmax, St[c * ST_STRIDE + r]);
            const float mold = smx[r];
            const float mnew = fmaxf(mold, tmax);
            const float al = __expf(mold - mnew);
            float sum = 0.0f;
#pragma unroll 8
            for (int c = 0; c < KT; c++) {
                float p = __expf(St[c * ST_STRIDE + r] - mnew);
                St[c * ST_STRIDE + r] = p;   // in-place: column r owned by this thread
                sum += p;
            }
            slv[r] = slv[r] * al + sum;
            smx[r] = mnew;
            sal[r] = al;
        }
        __syncthreads();

        // O = O*alpha + P V
#pragma unroll
        for (int i = 0; i < 8; i++) {
            const float al = sal[ty * 8 + i];
#pragma unroll
            for (int j = 0; j < 4; j++) acc[i][j] *= al;
        }
#pragma unroll 8
        for (int c = 0; c < KT; c++) {
            float4 p0 = *(const float4*)&St[c * ST_STRIDE + ty * 8];
            float4 p1 = *(const float4*)&St[c * ST_STRIDE + ty * 8 + 4];
            float4 vv = *(const float4*)&Vs[c * DD + tx * 4];
            float pa[8] = {p0.x, p0.y, p0.z, p0.w, p1.x, p1.y, p1.z, p1.w};
            float vb[4] = {vv.x, vv.y, vv.z, vv.w};
#pragma unroll
            for (int i = 0; i < 8; i++)
#pragma unroll
                for (int j = 0; j < 4; j++)
                    acc[i][j] += pa[i] * vb[j];
        }
    }

    // Normalize and write out: O[b][n][h*64+d]
#pragma unroll
    for (int i = 0; i < 8; i++) {
        const int r = ty * 8 + i;
        const float inv = 1.0f / slv[r];
        float4 o;
        o.x = acc[i][0] * inv; o.y = acc[i][1] * inv;
        o.z = acc[i][2] * inv; o.w = acc[i][3] * inv;
        *(float4*)(O + (size_t)(b * NN + qt * QT + r) * CDIM + h * DD + tx * 4) = o;
    }
}

// ---------------------------------------------------------------------------
// Launch
// ---------------------------------------------------------------------------
#define ATTN_SMEM_BYTES ((3 * DD * 64 + KT * ST_STRIDE + 3 * QT) * (int)sizeof(float))

extern "C" void kernel_launch(void* const* d_in, const int* in_sizes, int n_in,
                              void* d_out, int out_size)
{
    const float* x  = (const float*)d_in[0];   // [2,1024,1024]
    const float* y  = (const float*)d_in[1];   // [2,4096,1024]
    const float* Wq = (const float*)d_in[2];   // [1024,1024]
    const float* Wk = (const float*)d_in[3];
    const float* Wv = (const float*)d_in[4];
    const float* Wp = (const float*)d_in[5];
    const float* bp = (const float*)d_in[6];   // [1024]
    float* out = (float*)d_out;                // [2,1024,1024]

    float *Qb, *Kb, *Vb, *Ab;
    cudaGetSymbolAddress((void**)&Qb, g_Q);
    cudaGetSymbolAddress((void**)&Kb, g_K);
    cudaGetSymbolAddress((void**)&Vb, g_V);
    cudaGetSymbolAddress((void**)&Ab, g_Ao);

    cudaFuncSetAttribute(attn_kernel,
                         cudaFuncAttributeMaxDynamicSharedMemorySize,
                         ATTN_SMEM_BYTES);

    const int M1 = BB * NN;     // 2048
    const int M2 = BB * LLEN;   // 8192

    // Projections: q = x Wq^T, k = y Wk^T, v = y Wv^T
    gemm_abt<<<dim3(CDIM / 64, M1 / 64), 256>>>(Qb, x, Wq, nullptr, M1, CDIM, CDIM);
    gemm_abt<<<dim3(CDIM / 64, M2 / 64), 256>>>(Kb, y, Wk, nullptr, M2, CDIM, CDIM);
    gemm_abt<<<dim3(CDIM / 64, M2 / 64), 256>>>(Vb, y, Wv, nullptr, M2, CDIM, CDIM);

    // Flash attention: grid (qtiles, heads, batch)
    attn_kernel<<<dim3(NN / QT, HH, BB), 128, ATTN_SMEM_BYTES>>>(Ab, Qb, Kb, Vb);

    // Output projection with bias
    gemm_abt<<<dim3(CDIM / 64, M1 / 64), 256>>>(out, Ab, Wp, bp, M1, CDIM, CDIM);
}

// round 2
// speedup vs baseline: 1.0012x; 1.0012x over previous
#include <cuda_runtime.h>
#include <math.h>
#include <stdint.h>

// Problem shape (fixed by the dataset)
#define BB   2
#define NN   1024
#define LLEN 4096
#define CDIM 1024
#define HH   16
#define DD   64
#define ATTN_SCALE 0.125f   // 64^-0.5

// Scratch (device globals — no allocation allowed in kernel_launch)
__device__ float g_Q[BB * NN * CDIM];     // 8 MB
__device__ float g_K[BB * LLEN * CDIM];   // 32 MB
__device__ float g_V[BB * LLEN * CDIM];   // 32 MB
__device__ float g_Ao[BB * NN * CDIM];    // 8 MB

// ---------------------------------------------------------------------------
// GEMM: C[m][n] = sum_k A[m][k] * B[n][k]  (+ bias[n])
// Tile 64x64, BK=16, 256 threads, 4x4 register micro-tile per thread.
// ---------------------------------------------------------------------------
__global__ __launch_bounds__(256) void gemm_abt(
    float* __restrict__ C, const float* __restrict__ A,
    const float* __restrict__ B, const float* __restrict__ bias,
    int M, int N, int K)
{
    __shared__ float As[16][64];   // [k][m]
    __shared__ float Bs[16][64];   // [k][n]

    const int m0 = blockIdx.y * 64;
    const int n0 = blockIdx.x * 64;
    const int tid = threadIdx.x;
    const int tx = tid & 15;       // 0..15 -> n micro
    const int ty = tid >> 4;       // 0..15 -> m micro

    const int lr = tid >> 2;          // 0..63: tile row for loading
    const int lk = (tid & 3) << 2;    // 0,4,8,12: k offset (float4)

    const float* Ap = A + (size_t)(m0 + lr) * K + lk;
    const float* Bp = B + (size_t)(n0 + lr) * K + lk;

    float acc[4][4] = {};

    for (int k0 = 0; k0 < K; k0 += 16) {
        float4 a = *(const float4*)(Ap + k0);
        float4 b = *(const float4*)(Bp + k0);
        As[lk + 0][lr] = a.x; As[lk + 1][lr] = a.y;
        As[lk + 2][lr] = a.z; As[lk + 3][lr] = a.w;
        Bs[lk + 0][lr] = b.x; Bs[lk + 1][lr] = b.y;
        Bs[lk + 2][lr] = b.z; Bs[lk + 3][lr] = b.w;
        __syncthreads();

#pragma unroll
        for (int k = 0; k < 16; k++) {
            float4 av = *(const float4*)&As[k][ty * 4];
            float4 bv = *(const float4*)&Bs[k][tx * 4];
            float ar[4] = {av.x, av.y, av.z, av.w};
            float br[4] = {bv.x, bv.y, bv.z, bv.w};
#pragma unroll
            for (int i = 0; i < 4; i++)
#pragma unroll
                for (int j = 0; j < 4; j++)
                    acc[i][j] += ar[i] * br[j];
        }
        __syncthreads();
    }

#pragma unroll
    for (int i = 0; i < 4; i++) {
        const int m = m0 + ty * 4 + i;
        const int n = n0 + tx * 4;
        float4 o;
        o.x = acc[i][0]; o.y = acc[i][1]; o.z = acc[i][2]; o.w = acc[i][3];
        if (bias != nullptr) {
            o.x += bias[n + 0]; o.y += bias[n + 1];
            o.z += bias[n + 2]; o.w += bias[n + 3];
        }
        *(float4*)&C[(size_t)m * N + n] = o;
    }
}

// ---------------------------------------------------------------------------
// Flash attention (fp32). One block = 64 queries of one (b,h).
// 128 threads: 16(x: cols) x 8(y: rows). Streams L in tiles of 64 keys with
// online softmax. Q/K stored transposed [d][row] in smem for outer-product GEMM.
// ---------------------------------------------------------------------------
#define QT 64
#define KT 64
#define ST_STRIDE 68   // padded stride for S/P tile [c][r]

__global__ __launch_bounds__(128) void attn_kernel(
    float* __restrict__ O, const float* __restrict__ Q,
    const float* __restrict__ K, const float* __restrict__ V)
{
    extern __shared__ float smem[];
    float* Qs  = smem;                 // [DD][QT]   (transposed)
    float* Ks  = Qs  + DD * QT;        // [DD][KT]   (transposed)
    float* Vs  = Ks  + DD * KT;        // [KT][DD]   (row-major)
    float* St  = Vs  + KT * DD;        // [KT][ST_STRIDE]  S then P, [c][r]
    float* smx = St  + KT * ST_STRIDE; // [QT] running max
    float* slv = smx + QT;             // [QT] running sum
    float* sal = slv + QT;             // [QT] rescale factor

    const int tid = threadIdx.x;
    const int tx  = tid & 15;   // 0..15
    const int ty  = tid >> 4;   // 0..7
    const int qt = blockIdx.x;
    const int h  = blockIdx.y;
    const int b  = blockIdx.z;

    const float* Qg = Q + (size_t)(b * NN + qt * QT) * CDIM + h * DD;
    const float* Kg = K + (size_t)b * LLEN * CDIM + h * DD;
    const float* Vg = V + (size_t)b * LLEN * CDIM + h * DD;

    // Load Q tile, transposed into Qs[d][r]
    for (int i = tid; i < QT * (DD / 4); i += 128) {
        const int r  = i >> 4;            // query row 0..63
        const int dq = (i & 15) << 2;     // d offset 0..60
        float4 v = *(const float4*)(Qg + (size_t)r * CDIM + dq);
        Qs[(dq + 0) * QT + r] = v.x;
        Qs[(dq + 1) * QT + r] = v.y;
        Qs[(dq + 2) * QT + r] = v.z;
        Qs[(dq + 3) * QT + r] = v.w;
    }
    if (tid < QT) { smx[tid] = -1e30f; slv[tid] = 0.0f; }

    float acc[8][4] = {};   // O[r = ty*8+i][d = tx*4+j]

    for (int kt = 0; kt < LLEN / KT; kt++) {
        __syncthreads();   // protects Qs (first iter) and Ks/Vs/St reuse

        // Load K (transposed) and V (row-major) tiles
        const float* Kt_ = Kg + (size_t)(kt * KT) * CDIM;
        const float* Vt_ = Vg + (size_t)(kt * KT) * CDIM;
        for (int i = tid; i < KT * (DD / 4); i += 128) {
            const int r  = i >> 4;
            const int dq = (i & 15) << 2;
            float4 kv = *(const float4*)(Kt_ + (size_t)r * CDIM + dq);
            Ks[(dq + 0) * KT + r] = kv.x;
            Ks[(dq + 1) * KT + r] = kv.y;
            Ks[(dq + 2) * KT + r] = kv.z;
            Ks[(dq + 3) * KT + r] = kv.w;
            float4 vv = *(const float4*)(Vt_ + (size_t)r * CDIM + dq);
            *(float4*)&Vs[r * DD + dq] = vv;
        }
        __syncthreads();

        // S = Q K^T  (scaled), written transposed St[c][r]
        float s[8][4] = {};
#pragma unroll 8
        for (int d = 0; d < DD; d++) {
            float4 q0 = *(const float4*)&Qs[d * QT + ty * 8];
            float4 q1 = *(const float4*)&Qs[d * QT + ty * 8 + 4];
            float4 kc = *(const float4*)&Ks[d * KT + tx * 4];
            float qa[8] = {q0.x, q0.y, q0.z, q0.w, q1.x, q1.y, q1.z, q1.w};
            float kb[4] = {kc.x, kc.y, kc.z, kc.w};
#pragma unroll
            for (int i = 0; i < 8; i++)
#pragma unroll
                for (int j = 0; j < 4; j++)
                    s[i][j] += qa[i] * kb[j];
        }
#pragma unroll
        for (int i = 0; i < 8; i++)
#pragma unroll
            for (int j = 0; j < 4; j++)
                St[(tx * 4 + j) * ST_STRIDE + (ty * 8 + i)] = s[i][j] * ATTN_SCALE;
        __syncthreads();

        // Online softmax: thread r owns query row r (threads 0..63)
        if (tid < QT) {
            const int r = tid;
            float tmax = -1e30f;
#pragma unroll 8
            for (int c = 0; c < KT; c++)
                tmax = fmaxf(tmax, St[c * ST_STRIDE + r]);
            const float mold = smx[r];
            const float mnew = fmaxf(mold, tmax);
            const float al = __expf(mold - mnew);
            float sum = 0.0f;
#pragma unroll 8
            for (int c = 0; c < KT; c++) {
                float p = __expf(St[c * ST_STRIDE + r] - mnew);
                St[c * ST_STRIDE + r] = p;   // in-place: column r owned by this thread
                sum += p;
            }
            slv[r] = slv[r] * al + sum;
            smx[r] = mnew;
            sal[r] = al;
        }
        __syncthreads();

        // O = O*alpha + P V
#pragma unroll
        for (int i = 0; i < 8; i++) {
            const float al = sal[ty * 8 + i];
#pragma unroll
            for (int j = 0; j < 4; j++) acc[i][j] *= al;
        }
#pragma unroll 8
        for (int c = 0; c < KT; c++) {
            float4 p0 = *(const float4*)&St[c * ST_STRIDE + ty * 8];
            float4 p1 = *(const float4*)&St[c * ST_STRIDE + ty * 8 + 4];
            float4 vv = *(const float4*)&Vs[c * DD + tx * 4];
            float pa[8] = {p0.x, p0.y, p0.z, p0.w, p1.x, p1.y, p1.z, p1.w};
            float vb[4] = {vv.x, vv.y, vv.z, vv.w};
#pragma unroll
            for (int i = 0; i < 8; i++)
#pragma unroll
                for (int j = 0; j < 4; j++)
                    acc[i][j] += pa[i] * vb[j];
        }
    }

    // Normalize and write out: O[b][n][h*64+d]
#pragma unroll
    for (int i = 0; i < 8; i++) {
        const int r = ty * 8 + i;
        const float inv = 1.0f / slv[r];
        float4 o;
        o.x = acc[i][0] * inv; o.y = acc[i][1] * inv;
        o.z = acc[i][2] * inv; o.w = acc[i][3] * inv;
        *(float4*)(O + (size_t)(b * NN + qt * QT + r) * CDIM + h * DD + tx * 4) = o;
    }
}

// ---------------------------------------------------------------------------
// Launch
// ---------------------------------------------------------------------------
#define ATTN_SMEM_BYTES ((3 * DD * 64 + KT * ST_STRIDE + 3 * QT) * (int)sizeof(float))

extern "C" void kernel_launch(void* const* d_in, const int* in_sizes, int n_in,
                              void* d_out, int out_size)
{
    const float* x  = (const float*)d_in[0];   // [2,1024,1024]
    const float* y  = (const float*)d_in[1];   // [2,4096,1024]
    const float* Wq = (const float*)d_in[2];   // [1024,1024]
    const float* Wk = (const float*)d_in[3];
    const float* Wv = (const float*)d_in[4];
    const float* Wp = (const float*)d_in[5];
    const float* bp = (const float*)d_in[6];   // [1024]
    float* out = (float*)d_out;                // [2,1024,1024]

    float *Qb, *Kb, *Vb, *Ab;
    cudaGetSymbolAddress((void**)&Qb, g_Q);
    cudaGetSymbolAddress((void**)&Kb, g_K);
    cudaGetSymbolAddress((void**)&Vb, g_V);
    cudaGetSymbolAddress((void**)&Ab, g_Ao);

    cudaFuncSetAttribute(attn_kernel,
                         cudaFuncAttributeMaxDynamicSharedMemorySize,
                         ATTN_SMEM_BYTES);

    const int M1 = BB * NN;     // 2048
    const int M2 = BB * LLEN;   // 8192

    // Projections: q = x Wq^T, k = y Wk^T, v = y Wv^T
    gemm_abt<<<dim3(CDIM / 64, M1 / 64), 256>>>(Qb, x, Wq, nullptr, M1, CDIM, CDIM);
    gemm_abt<<<dim3(CDIM / 64, M2 / 64), 256>>>(Kb, y, Wk, nullptr, M2, CDIM, CDIM);
    gemm_abt<<<dim3(CDIM / 64, M2 / 64), 256>>>(Vb, y, Wv, nullptr, M2, CDIM, CDIM);

    // Flash attention: grid (qtiles, heads, batch)
    attn_kernel<<<dim3(NN / QT, HH, BB), 128, ATTN_SMEM_BYTES>>>(Ab, Qb, Kb, Vb);

    // Output projection with bias
    gemm_abt<<<dim3(CDIM / 64, M1 / 64), 256>>>(out, Ab, Wp, bp, M1, CDIM, CDIM);
}

// round 5
// speedup vs baseline: 1.3656x; 1.3640x over previous
#include <cuda_runtime.h>
#include <cuda_bf16.h>
#include <math.h>
#include <stdint.h>

// Problem shape (fixed by the dataset)
#define BB   2
#define NN   1024
#define LLEN 4096
#define CDIM 1024
#define HH   16
#define DD   64
#define ATTN_SCALE 0.125f   // 64^-0.5

// ---------------- scratch (device globals; no allocs allowed) ---------------
__device__ float g_Q[BB * NN * CDIM];     // 8 MB
__device__ float g_K[BB * LLEN * CDIM];   // 32 MB
__device__ float g_V[BB * LLEN * CDIM];   // 32 MB
__device__ float g_Ao[BB * NN * CDIM];    // 8 MB

// bf16 hi/lo splits
__device__ __nv_bfloat16 g_xh[BB * NN * CDIM],   g_xl[BB * NN * CDIM];
__device__ __nv_bfloat16 g_yh[BB * LLEN * CDIM], g_yl[BB * LLEN * CDIM];
__device__ __nv_bfloat16 g_wh[4 * CDIM * CDIM],  g_wl[4 * CDIM * CDIM];
__device__ __nv_bfloat16 g_aoh[BB * NN * CDIM],  g_aol[BB * NN * CDIM];

// single shared-memory extern symbol for the whole TU
extern __shared__ char dsm[];

// ---------------------------------------------------------------------------
// helpers
// ---------------------------------------------------------------------------
static __device__ __forceinline__ uint32_t smem_u32(const void* p) {
    uint32_t a;
    asm("{ .reg .u64 t; cvta.to.shared.u64 t, %1; cvt.u32.u64 %0, t; }"
        : "=r"(a) : "l"(p));
    return a;
}
static __device__ __forceinline__ void cp16(uint32_t dst, const void* src) {
    asm volatile("cp.async.cg.shared.global [%0], [%1], 16;"
                 :: "r"(dst), "l"(src));
}
static __device__ __forceinline__ void cp_commit() {
    asm volatile("cp.async.commit_group;" ::: "memory");
}
template <int N_>
static __device__ __forceinline__ void cp_wait() {
    asm volatile("cp.async.wait_group %0;" :: "n"(N_) : "memory");
}
// mma.sync bf16 m16n8k16, row.col, fp32 accumulate
static __device__ __forceinline__ void mma_bf16(
    float* c, uint32_t a0, uint32_t a1, uint32_t a2, uint32_t a3,
    uint32_t b0, uint32_t b1)
{
    asm volatile(
        "mma.sync.aligned.m16n8k16.row.col.f32.bf16.bf16.f32 "
        "{%0,%1,%2,%3}, {%4,%5,%6,%7}, {%8,%9}, {%0,%1,%2,%3};"
        : "+f"(c[0]), "+f"(c[1]), "+f"(c[2]), "+f"(c[3])
        : "r"(a0), "r"(a1), "r"(a2), "r"(a3), "r"(b0), "r"(b1));
}

// ---------------------------------------------------------------------------
// split: fp32 -> bf16 hi + bf16 lo (residual)
// ---------------------------------------------------------------------------
__global__ void split_bf16(const float* __restrict__ src,
                           __nv_bfloat16* __restrict__ hi,
                           __nv_bfloat16* __restrict__ lo, int n4)
{
    int i = blockIdx.x * blockDim.x + threadIdx.x;
    if (i >= n4) return;
    float4 v = ((const float4*)src)[i];
    __nv_bfloat16 h0 = __float2bfloat16(v.x);
    __nv_bfloat16 h1 = __float2bfloat16(v.y);
    __nv_bfloat16 h2 = __float2bfloat16(v.z);
    __nv_bfloat16 h3 = __float2bfloat16(v.w);
    __nv_bfloat162 hh0; hh0.x = h0; hh0.y = h1;
    __nv_bfloat162 hh1; hh1.x = h2; hh1.y = h3;
    __nv_bfloat162 ll0, ll1;
    ll0.x = __float2bfloat16(v.x - __bfloat162float(h0));
    ll0.y = __float2bfloat16(v.y - __bfloat162float(h1));
    ll1.x = __float2bfloat16(v.z - __bfloat162float(h2));
    ll1.y = __float2bfloat16(v.w - __bfloat162float(h3));
    ((__nv_bfloat162*)hi)[i * 2 + 0] = hh0;
    ((__nv_bfloat162*)hi)[i * 2 + 1] = hh1;
    ((__nv_bfloat162*)lo)[i * 2 + 0] = ll0;
    ((__nv_bfloat162*)lo)[i * 2 + 1] = ll1;
}

// ---------------------------------------------------------------------------
// mma.sync GEMM (bf16x3 split): C[m][n] = sum_k A[m][k]*B[n][k] (+bias[n])
// CTA tile 128x128, BK=32, 256 threads (8 warps, 4m x 2n, warp = 32m x 64n).
// Smem rows padded to 40 bf16 (80B): fragment lds conflict-free.
// cp.async double buffering.
// ---------------------------------------------------------------------------
#define RPAD   40                      // bf16 per smem row (32 used)
#define ROWB   80                      // bytes per row
#define ROWW   20                      // words per row
#define TILEB  (128 * ROWB)            // 10240 B per operand tile
#define TILEW  (TILEB / 4)
#define STAGEB (4 * TILEB)             // Ah, Al, Bh, Bl
#define GEMM_SMEM (2 * STAGEB)         // 81920 B

__global__ __launch_bounds__(256, 1)
void gemm_mma(float* __restrict__ C,
              const __nv_bfloat16* __restrict__ Ah, const __nv_bfloat16* __restrict__ Al,
              const __nv_bfloat16* __restrict__ Bh, const __nv_bfloat16* __restrict__ Bl,
              const float* __restrict__ bias, int M, int N, int K)
{
    const int tid  = threadIdx.x;
    const int wid  = tid >> 5;
    const int lane = tid & 31;
    const int wm   = wid & 3;          // 4 warps in m: 32 rows each
    const int wn   = wid >> 2;         // 2 warps in n: 64 cols each
    const int g    = lane >> 2;        // 0..7
    const int t4   = lane & 3;         // 0..3
    const int m0   = blockIdx.y * 128;
    const int n0   = blockIdx.x * 128;

    const uint32_t sb = smem_u32(dsm);

    // ---- cp.async load mapping: tile = tid/64, rows lrow & lrow+64 ----
    const int tsel = tid >> 6;
    const int lrow = tid & 63;
    const int segr = (tid >> 3) & 3;   // segment rotation: conflict-free STS
    const __nv_bfloat16* gsrc =
        (tsel == 0) ? Ah : (tsel == 1) ? Al : (tsel == 2) ? Bh : Bl;
    const int trow0 = (tsel < 2) ? m0 : n0;
    const __nv_bfloat16* gp0 = gsrc + (size_t)(trow0 + lrow) * K;
    const __nv_bfloat16* gp1 = gp0 + (size_t)64 * K;
    const uint32_t sd0 = sb + tsel * TILEB + lrow * ROWB;
    const uint32_t sd1 = sd0 + 64 * ROWB;

    const int nchunk = K >> 5;         // K / 32

#define LOAD_STAGE(cc, buf) do {                                              \
        const uint32_t bo = (uint32_t)(buf) * STAGEB;                         \
        _Pragma("unroll")                                                     \
        for (int s = 0; s < 4; s++) {                                         \
            const int seg = (s + segr) & 3;                                   \
            cp16(sd0 + bo + seg * 16, gp0 + (cc) * 32 + seg * 8);             \
            cp16(sd1 + bo + seg * 16, gp1 + (cc) * 32 + seg * 8);             \
        }                                                                     \
    } while (0)

    float acc[2][8][4];
#pragma unroll
    for (int mf = 0; mf < 2; mf++)
#pragma unroll
        for (int nf = 0; nf < 8; nf++)
#pragma unroll
            for (int j = 0; j < 4; j++) acc[mf][nf][j] = 0.0f;

    LOAD_STAGE(0, 0);
    cp_commit();

    for (int c = 0; c < nchunk; c++) {
        const int buf = c & 1;
        if (c + 1 < nchunk) {
            LOAD_STAGE(c + 1, buf ^ 1);
            cp_commit();
            cp_wait<1>();
        } else {
            cp_wait<0>();
        }
        __syncthreads();

        const uint32_t* S   = (const uint32_t*)(dsm + buf * STAGEB);
        const uint32_t* pAh = S;
        const uint32_t* pAl = S + TILEW;
        const uint32_t* pBh = S + 2 * TILEW;
        const uint32_t* pBl = S + 3 * TILEW;

#pragma unroll
        for (int ks = 0; ks < 2; ks++) {
            const int kw = ks * 8;     // word offset of this k16 step
            uint32_t ah[2][4], al[2][4], bh[8][2], bl[8][2];
#pragma unroll
            for (int mf = 0; mf < 2; mf++) {
                const int r = (wm * 32 + mf * 16 + g) * ROWW + t4 + kw;
                ah[mf][0] = pAh[r];
                ah[mf][1] = pAh[r + 8 * ROWW];
                ah[mf][2] = pAh[r + 4];
                ah[mf][3] = pAh[r + 8 * ROWW + 4];
                al[mf][0] = pAl[r];
                al[mf][1] = pAl[r + 8 * ROWW];
                al[mf][2] = pAl[r + 4];
                al[mf][3] = pAl[r + 8 * ROWW + 4];
            }
#pragma unroll
            for (int nf = 0; nf < 8; nf++) {
                const int r = (wn * 64 + nf * 8 + g) * ROWW + t4 + kw;
                bh[nf][0] = pBh[r];
                bh[nf][1] = pBh[r + 4];
                bl[nf][0] = pBl[r];
                bl[nf][1] = pBl[r + 4];
            }
#pragma unroll
            for (int mf = 0; mf < 2; mf++)
#pragma unroll
                for (int nf = 0; nf < 8; nf++) {
                    mma_bf16(acc[mf][nf], ah[mf][0], ah[mf][1], ah[mf][2], ah[mf][3],
                             bh[nf][0], bh[nf][1]);
                    mma_bf16(acc[mf][nf], ah[mf][0], ah[mf][1], ah[mf][2], ah[mf][3],
                             bl[nf][0], bl[nf][1]);
                    mma_bf16(acc[mf][nf], al[mf][0], al[mf][1], al[mf][2], al[mf][3],
                             bh[nf][0], bh[nf][1]);
                }
        }
        __syncthreads();
    }

    // Epilogue: direct register -> gmem stores (float2 pairs)
#pragma unroll
    for (int mf = 0; mf < 2; mf++) {
        const int row = m0 + wm * 32 + mf * 16 + g;
#pragma unroll
        for (int nf = 0; nf < 8; nf++) {
            const int col = n0 + wn * 64 + nf * 8 + 2 * t4;
            float b0 = 0.0f, b1 = 0.0f;
            if (bias) { b0 = bias[col]; b1 = bias[col + 1]; }
            float2 v0, v1;
            v0.x = acc[mf][nf][0] + b0; v0.y = acc[mf][nf][1] + b1;
            v1.x = acc[mf][nf][2] + b0; v1.y = acc[mf][nf][3] + b1;
            *(float2*)&C[(size_t)row * N + col]       = v0;
            *(float2*)&C[(size_t)(row + 8) * N + col] = v1;
        }
    }
#undef LOAD_STAGE
}

// ---------------------------------------------------------------------------
// Flash attention (fp32) — unchanged (proven correct)
// ---------------------------------------------------------------------------
#define QT 64
#define KT 64
#define ST_STRIDE 68

__global__ __launch_bounds__(128) void attn_kernel(
    float* __restrict__ O, const float* __restrict__ Q,
    const float* __restrict__ K, const float* __restrict__ V)
{
    float* smem = (float*)dsm;
    float* Qs  = smem;
    float* Ks  = Qs  + DD * QT;
    float* Vs  = Ks  + DD * KT;
    float* St  = Vs  + KT * DD;
    float* smx = St  + KT * ST_STRIDE;
    float* slv = smx + QT;
    float* sal = slv + QT;

    const int tid = threadIdx.x;
    const int tx  = tid & 15;
    const int ty  = tid >> 4;
    const int qt = blockIdx.x;
    const int h  = blockIdx.y;
    const int b  = blockIdx.z;

    const float* Qg = Q + (size_t)(b * NN + qt * QT) * CDIM + h * DD;
    const float* Kg = K + (size_t)b * LLEN * CDIM + h * DD;
    const float* Vg = V + (size_t)b * LLEN * CDIM + h * DD;

    for (int i = tid; i < QT * (DD / 4); i += 128) {
        const int r  = i >> 4;
        const int dq = (i & 15) << 2;
        float4 v = *(const float4*)(Qg + (size_t)r * CDIM + dq);
        Qs[(dq + 0) * QT + r] = v.x;
        Qs[(dq + 1) * QT + r] = v.y;
        Qs[(dq + 2) * QT + r] = v.z;
        Qs[(dq + 3) * QT + r] = v.w;
    }
    if (tid < QT) { smx[tid] = -1e30f; slv[tid] = 0.0f; }

    float acc[8][4] = {};

    for (int kt = 0; kt < LLEN / KT; kt++) {
        __syncthreads();

        const float* Kt_ = Kg + (size_t)(kt * KT) * CDIM;
        const float* Vt_ = Vg + (size_t)(kt * KT) * CDIM;
        for (int i = tid; i < KT * (DD / 4); i += 128) {
            const int r  = i >> 4;
            const int dq = (i & 15) << 2;
            float4 kv = *(const float4*)(Kt_ + (size_t)r * CDIM + dq);
            Ks[(dq + 0) * KT + r] = kv.x;
            Ks[(dq + 1) * KT + r] = kv.y;
            Ks[(dq + 2) * KT + r] = kv.z;
            Ks[(dq + 3) * KT + r] = kv.w;
            float4 vv = *(const float4*)(Vt_ + (size_t)r * CDIM + dq);
            *(float4*)&Vs[r * DD + dq] = vv;
        }
        __syncthreads();

        float s[8][4] = {};
#pragma unroll 8
        for (int d = 0; d < DD; d++) {
            float4 q0 = *(const float4*)&Qs[d * QT + ty * 8];
            float4 q1 = *(const float4*)&Qs[d * QT + ty * 8 + 4];
            float4 kc = *(const float4*)&Ks[d * KT + tx * 4];
            float qa[8] = {q0.x, q0.y, q0.z, q0.w, q1.x, q1.y, q1.z, q1.w};
            float kb[4] = {kc.x, kc.y, kc.z, kc.w};
#pragma unroll
            for (int i = 0; i < 8; i++)
#pragma unroll
                for (int j = 0; j < 4; j++)
                    s[i][j] += qa[i] * kb[j];
        }
#pragma unroll
        for (int i = 0; i < 8; i++)
#pragma unroll
            for (int j = 0; j < 4; j++)
                St[(tx * 4 + j) * ST_STRIDE + (ty * 8 + i)] = s[i][j] * ATTN_SCALE;
        __syncthreads();

        if (tid < QT) {
            const int r = tid;
            float tmax = -1e30f;
#pragma unroll 8
            for (int c = 0; c < KT; c++)
                tmax = fmaxf(tmax, St[c * ST_STRIDE + r]);
            const float mold = smx[r];
            const float mnew = fmaxf(mold, tmax);
            const float al = __expf(mold - mnew);
            float sum = 0.0f;
#pragma unroll 8
            for (int c = 0; c < KT; c++) {
                float p = __expf(St[c * ST_STRIDE + r] - mnew);
                St[c * ST_STRIDE + r] = p;
                sum += p;
            }
            slv[r] = slv[r] * al + sum;
            smx[r] = mnew;
            sal[r] = al;
        }
        __syncthreads();

#pragma unroll
        for (int i = 0; i < 8; i++) {
            const float al = sal[ty * 8 + i];
#pragma unroll
            for (int j = 0; j < 4; j++) acc[i][j] *= al;
        }
#pragma unroll 8
        for (int c = 0; c < KT; c++) {
            float4 p0 = *(const float4*)&St[c * ST_STRIDE + ty * 8];
            float4 p1 = *(const float4*)&St[c * ST_STRIDE + ty * 8 + 4];
            float4 vv = *(const float4*)&Vs[c * DD + tx * 4];
            float pa[8] = {p0.x, p0.y, p0.z, p0.w, p1.x, p1.y, p1.z, p1.w};
            float vb[4] = {vv.x, vv.y, vv.z, vv.w};
#pragma unroll
            for (int i = 0; i < 8; i++)
#pragma unroll
                for (int j = 0; j < 4; j++)
                    acc[i][j] += pa[i] * vb[j];
        }
    }

#pragma unroll
    for (int i = 0; i < 8; i++) {
        const int r = ty * 8 + i;
        const float inv = 1.0f / slv[r];
        float4 o;
        o.x = acc[i][0] * inv; o.y = acc[i][1] * inv;
        o.z = acc[i][2] * inv; o.w = acc[i][3] * inv;
        *(float4*)(O + (size_t)(b * NN + qt * QT + r) * CDIM + h * DD + tx * 4) = o;
    }
}

#define ATTN_SMEM_BYTES ((3 * DD * 64 + KT * ST_STRIDE + 3 * QT) * (int)sizeof(float))

// ---------------------------------------------------------------------------
// Launch
// ---------------------------------------------------------------------------
extern "C" void kernel_launch(void* const* d_in, const int* in_sizes, int n_in,
                              void* d_out, int out_size)
{
    const float* x  = (const float*)d_in[0];
    const float* y  = (const float*)d_in[1];
    const float* Wq = (const float*)d_in[2];
    const float* Wk = (const float*)d_in[3];
    const float* Wv = (const float*)d_in[4];
    const float* Wp = (const float*)d_in[5];
    const float* bp = (const float*)d_in[6];
    float* out = (float*)d_out;

    float *Qb, *Kb, *Vb, *Ab;
    cudaGetSymbolAddress((void**)&Qb, g_Q);
    cudaGetSymbolAddress((void**)&Kb, g_K);
    cudaGetSymbolAddress((void**)&Vb, g_V);
    cudaGetSymbolAddress((void**)&Ab, g_Ao);
    __nv_bfloat16 *xh, *xl, *yh, *yl, *wh, *wl, *aoh, *aol;
    cudaGetSymbolAddress((void**)&xh, g_xh);
    cudaGetSymbolAddress((void**)&xl, g_xl);
    cudaGetSymbolAddress((void**)&yh, g_yh);
    cudaGetSymbolAddress((void**)&yl, g_yl);
    cudaGetSymbolAddress((void**)&wh, g_wh);
    cudaGetSymbolAddress((void**)&wl, g_wl);
    cudaGetSymbolAddress((void**)&aoh, g_aoh);
    cudaGetSymbolAddress((void**)&aol, g_aol);

    cudaFuncSetAttribute(attn_kernel, cudaFuncAttributeMaxDynamicSharedMemorySize,
                         ATTN_SMEM_BYTES);
    cudaFuncSetAttribute(gemm_mma, cudaFuncAttributeMaxDynamicSharedMemorySize,
                         GEMM_SMEM);

    const int M1 = BB * NN;     // 2048
    const int M2 = BB * LLEN;   // 8192
    const int WSZ = CDIM * CDIM;

    // Splits (fp32 -> bf16 hi/lo)
    {
        int n4;
        n4 = (M1 * CDIM) / 4;
        split_bf16<<<(n4 + 255) / 256, 256>>>(x, xh, xl, n4);
        n4 = (M2 * CDIM) / 4;
        split_bf16<<<(n4 + 255) / 256, 256>>>(y, yh, yl, n4);
        n4 = WSZ / 4;
        split_bf16<<<(n4 + 255) / 256, 256>>>(Wq, wh + 0 * WSZ, wl + 0 * WSZ, n4);
        split_bf16<<<(n4 + 255) / 256, 256>>>(Wk, wh + 1 * WSZ, wl + 1 * WSZ, n4);
        split_bf16<<<(n4 + 255) / 256, 256>>>(Wv, wh + 2 * WSZ, wl + 2 * WSZ, n4);
        split_bf16<<<(n4 + 255) / 256, 256>>>(Wp, wh + 3 * WSZ, wl + 3 * WSZ, n4);
    }

    // Projections on mma.sync tensor cores (bf16x3 split, fp32 accumulate)
    gemm_mma<<<dim3(CDIM / 128, M1 / 128), 256, GEMM_SMEM>>>(
        Qb, xh, xl, wh + 0 * WSZ, wl + 0 * WSZ, nullptr, M1, CDIM, CDIM);
    gemm_mma<<<dim3(CDIM / 128, M2 / 128), 256, GEMM_SMEM>>>(
        Kb, yh, yl, wh + 1 * WSZ, wl + 1 * WSZ, nullptr, M2, CDIM, CDIM);
    gemm_mma<<<dim3(CDIM / 128, M2 / 128), 256, GEMM_SMEM>>>(
        Vb, yh, yl, wh + 2 * WSZ, wl + 2 * WSZ, nullptr, M2, CDIM, CDIM);

    // Flash attention (fp32)
    attn_kernel<<<dim3(NN / QT, HH, BB), 128, ATTN_SMEM_BYTES>>>(Ab, Qb, Kb, Vb);

    // Split attention output, then output projection with bias
    {
        int n4 = (M1 * CDIM) / 4;
        split_bf16<<<(n4 + 255) / 256, 256>>>(Ab, aoh, aol, n4);
    }
    gemm_mma<<<dim3(CDIM / 128, M1 / 128), 256, GEMM_SMEM>>>(
        out, aoh, aol, wh + 3 * WSZ, wl + 3 * WSZ, bp, M1, CDIM, CDIM);
}

// round 6
// speedup vs baseline: 2.3238x; 1.7017x over previous
#include <cuda_runtime.h>
#include <cuda_bf16.h>
#include <math.h>
#include <stdint.h>

// Problem shape (fixed by the dataset)
#define BB   2
#define NN   1024
#define LLEN 4096
#define CDIM 1024
#define HH   16
#define DD   64
#define ATTN_SCALE 0.125f   // 64^-0.5

// ---------------- scratch (device globals; no allocs allowed) ---------------
__device__ __nv_bfloat16 g_xh[BB * NN * CDIM],   g_xl[BB * NN * CDIM];
__device__ __nv_bfloat16 g_yh[BB * LLEN * CDIM], g_yl[BB * LLEN * CDIM];
__device__ __nv_bfloat16 g_wh[4 * CDIM * CDIM],  g_wl[4 * CDIM * CDIM];
__device__ __nv_bfloat16 g_qh[BB * NN * CDIM],   g_ql[BB * NN * CDIM];
__device__ __nv_bfloat16 g_kh[BB * LLEN * CDIM], g_kl[BB * LLEN * CDIM];
__device__ __nv_bfloat16 g_vh[BB * LLEN * CDIM], g_vl[BB * LLEN * CDIM];
__device__ __nv_bfloat16 g_aoh[BB * NN * CDIM],  g_aol[BB * NN * CDIM];

extern __shared__ char dsm[];

// ---------------------------------------------------------------------------
// helpers
// ---------------------------------------------------------------------------
static __device__ __forceinline__ uint32_t smem_u32(const void* p) {
    uint32_t a;
    asm("{ .reg .u64 t; cvta.to.shared.u64 t, %1; cvt.u32.u64 %0, t; }"
        : "=r"(a) : "l"(p));
    return a;
}
static __device__ __forceinline__ void cp16(uint32_t dst, const void* src) {
    asm volatile("cp.async.cg.shared.global [%0], [%1], 16;"
                 :: "r"(dst), "l"(src));
}
static __device__ __forceinline__ void cp_commit() {
    asm volatile("cp.async.commit_group;" ::: "memory");
}
template <int N_>
static __device__ __forceinline__ void cp_wait() {
    asm volatile("cp.async.wait_group %0;" :: "n"(N_) : "memory");
}
// mma.sync bf16 m16n8k16, row.col, fp32 accumulate
static __device__ __forceinline__ void mma_bf16(
    float* c, uint32_t a0, uint32_t a1, uint32_t a2, uint32_t a3,
    uint32_t b0, uint32_t b1)
{
    asm volatile(
        "mma.sync.aligned.m16n8k16.row.col.f32.bf16.bf16.f32 "
        "{%0,%1,%2,%3}, {%4,%5,%6,%7}, {%8,%9}, {%0,%1,%2,%3};"
        : "+f"(c[0]), "+f"(c[1]), "+f"(c[2]), "+f"(c[3])
        : "r"(a0), "r"(a1), "r"(a2), "r"(a3), "r"(b0), "r"(b1));
}
// pack two floats into bf16x2 hi, and residual lo
static __device__ __forceinline__ void pack_hl(
    float a, float b, uint32_t& hi, uint32_t& lo)
{
    __nv_bfloat162 h = __floats2bfloat162_rn(a, b);   // .x=a (low), .y=b
    __nv_bfloat162 l = __floats2bfloat162_rn(a - __bfloat162float(h.x),
                                             b - __bfloat162float(h.y));
    hi = *(uint32_t*)&h;
    lo = *(uint32_t*)&l;
}

// ---------------------------------------------------------------------------
// split: fp32 -> bf16 hi + bf16 lo (residual)
// ---------------------------------------------------------------------------
__global__ void split_bf16(const float* __restrict__ src,
                           __nv_bfloat16* __restrict__ hi,
                           __nv_bfloat16* __restrict__ lo, int n4)
{
    int i = blockIdx.x * blockDim.x + threadIdx.x;
    if (i >= n4) return;
    float4 v = ((const float4*)src)[i];
    __nv_bfloat162 hh0 = __floats2bfloat162_rn(v.x, v.y);
    __nv_bfloat162 hh1 = __floats2bfloat162_rn(v.z, v.w);
    __nv_bfloat162 ll0 = __floats2bfloat162_rn(v.x - __bfloat162float(hh0.x),
                                               v.y - __bfloat162float(hh0.y));
    __nv_bfloat162 ll1 = __floats2bfloat162_rn(v.z - __bfloat162float(hh1.x),
                                               v.w - __bfloat162float(hh1.y));
    ((__nv_bfloat162*)hi)[i * 2 + 0] = hh0;
    ((__nv_bfloat162*)hi)[i * 2 + 1] = hh1;
    ((__nv_bfloat162*)lo)[i * 2 + 0] = ll0;
    ((__nv_bfloat162*)lo)[i * 2 + 1] = ll1;
}

// ---------------------------------------------------------------------------
// mma.sync GEMM (bf16x3 split): C[m][n] = sum_k A[m][k]*B[n][k] (+bias[n])
// CTA tile 128x128, BK=32, 256 threads (8 warps, 4m x 2n).
// OUTF32: fp32 C (+bias).  else: bf16 hi/lo outputs Ch, Cl.
// ---------------------------------------------------------------------------
#define ROWB   80                      // bytes per smem row (32 bf16 + pad)
#define ROWW   20                      // words per row
#define TILEB  (128 * ROWB)
#define TILEW  (TILEB / 4)
#define STAGEB (4 * TILEB)
#define GEMM_SMEM (2 * STAGEB)         // 81920 B

template <bool OUTF32>
__global__ __launch_bounds__(256, 1)
void gemm_mma(float* __restrict__ C,
              __nv_bfloat16* __restrict__ Ch, __nv_bfloat16* __restrict__ Cl,
              const __nv_bfloat16* __restrict__ Ah, const __nv_bfloat16* __restrict__ Al,
              const __nv_bfloat16* __restrict__ Bh, const __nv_bfloat16* __restrict__ Bl,
              const float* __restrict__ bias, int M, int N, int K)
{
    const int tid  = threadIdx.x;
    const int wid  = tid >> 5;
    const int lane = tid & 31;
    const int wm   = wid & 3;
    const int wn   = wid >> 2;
    const int g    = lane >> 2;
    const int t4   = lane & 3;
    const int m0   = blockIdx.y * 128;
    const int n0   = blockIdx.x * 128;

    const uint32_t sb = smem_u32(dsm);

    const int tsel = tid >> 6;
    const int lrow = tid & 63;
    const int segr = (tid >> 3) & 3;
    const __nv_bfloat16* gsrc =
        (tsel == 0) ? Ah : (tsel == 1) ? Al : (tsel == 2) ? Bh : Bl;
    const int trow0 = (tsel < 2) ? m0 : n0;
    const __nv_bfloat16* gp0 = gsrc + (size_t)(trow0 + lrow) * K;
    const __nv_bfloat16* gp1 = gp0 + (size_t)64 * K;
    const uint32_t sd0 = sb + tsel * TILEB + lrow * ROWB;
    const uint32_t sd1 = sd0 + 64 * ROWB;

    const int nchunk = K >> 5;

#define LOAD_STAGE(cc, buf) do {                                              \
        const uint32_t bo = (uint32_t)(buf) * STAGEB;                         \
        _Pragma("unroll")                                                     \
        for (int s = 0; s < 4; s++) {                                         \
            const int seg = (s + segr) & 3;                                   \
            cp16(sd0 + bo + seg * 16, gp0 + (cc) * 32 + seg * 8);             \
            cp16(sd1 + bo + seg * 16, gp1 + (cc) * 32 + seg * 8);             \
        }                                                                     \
    } while (0)

    float acc[2][8][4];
#pragma unroll
    for (int mf = 0; mf < 2; mf++)
#pragma unroll
        for (int nf = 0; nf < 8; nf++)
#pragma unroll
            for (int j = 0; j < 4; j++) acc[mf][nf][j] = 0.0f;

    LOAD_STAGE(0, 0);
    cp_commit();

    for (int c = 0; c < nchunk; c++) {
        const int buf = c & 1;
        if (c + 1 < nchunk) {
            LOAD_STAGE(c + 1, buf ^ 1);
            cp_commit();
            cp_wait<1>();
        } else {
            cp_wait<0>();
        }
        __syncthreads();

        const uint32_t* S   = (const uint32_t*)(dsm + buf * STAGEB);
        const uint32_t* pAh = S;
        const uint32_t* pAl = S + TILEW;
        const uint32_t* pBh = S + 2 * TILEW;
        const uint32_t* pBl = S + 3 * TILEW;

#pragma unroll
        for (int ks = 0; ks < 2; ks++) {
            const int kw = ks * 8;
            uint32_t ah[2][4], al[2][4], bh[8][2], bl[8][2];
#pragma unroll
            for (int mf = 0; mf < 2; mf++) {
                const int r = (wm * 32 + mf * 16 + g) * ROWW + t4 + kw;
                ah[mf][0] = pAh[r];
                ah[mf][1] = pAh[r + 8 * ROWW];
                ah[mf][2] = pAh[r + 4];
                ah[mf][3] = pAh[r + 8 * ROWW + 4];
                al[mf][0] = pAl[r];
                al[mf][1] = pAl[r + 8 * ROWW];
                al[mf][2] = pAl[r + 4];
                al[mf][3] = pAl[r + 8 * ROWW + 4];
            }
#pragma unroll
            for (int nf = 0; nf < 8; nf++) {
                const int r = (wn * 64 + nf * 8 + g) * ROWW + t4 + kw;
                bh[nf][0] = pBh[r];
                bh[nf][1] = pBh[r + 4];
                bl[nf][0] = pBl[r];
                bl[nf][1] = pBl[r + 4];
            }
#pragma unroll
            for (int mf = 0; mf < 2; mf++)
#pragma unroll
                for (int nf = 0; nf < 8; nf++) {
                    mma_bf16(acc[mf][nf], ah[mf][0], ah[mf][1], ah[mf][2], ah[mf][3],
                             bh[nf][0], bh[nf][1]);
                    mma_bf16(acc[mf][nf], ah[mf][0], ah[mf][1], ah[mf][2], ah[mf][3],
                             bl[nf][0], bl[nf][1]);
                    mma_bf16(acc[mf][nf], al[mf][0], al[mf][1], al[mf][2], al[mf][3],
                             bh[nf][0], bh[nf][1]);
                }
        }
        __syncthreads();
    }

#pragma unroll
    for (int mf = 0; mf < 2; mf++) {
        const int row = m0 + wm * 32 + mf * 16 + g;
#pragma unroll
        for (int nf = 0; nf < 8; nf++) {
            const int col = n0 + wn * 64 + nf * 8 + 2 * t4;
            if (OUTF32) {
                float b0 = 0.0f, b1 = 0.0f;
                if (bias) { b0 = bias[col]; b1 = bias[col + 1]; }
                float2 v0, v1;
                v0.x = acc[mf][nf][0] + b0; v0.y = acc[mf][nf][1] + b1;
                v1.x = acc[mf][nf][2] + b0; v1.y = acc[mf][nf][3] + b1;
                *(float2*)&C[(size_t)row * N + col]       = v0;
                *(float2*)&C[(size_t)(row + 8) * N + col] = v1;
            } else {
                uint32_t h0, l0, h1, l1;
                pack_hl(acc[mf][nf][0], acc[mf][nf][1], h0, l0);
                pack_hl(acc[mf][nf][2], acc[mf][nf][3], h1, l1);
                *(uint32_t*)&Ch[(size_t)row * N + col]       = h0;
                *(uint32_t*)&Cl[(size_t)row * N + col]       = l0;
                *(uint32_t*)&Ch[(size_t)(row + 8) * N + col] = h1;
                *(uint32_t*)&Cl[(size_t)(row + 8) * N + col] = l1;
            }
        }
    }
#undef LOAD_STAGE
}

// ---------------------------------------------------------------------------
// Flash attention on mma.sync (bf16x3).  CTA = 128 queries of one (b,h).
// 8 warps x 16 rows; warp-local online softmax.  KT=64 key chunks,
// double-buffered: K via cp.async, V via LDG + transposed STS ([d][key]).
// Outputs bf16 hi/lo for the final projection.
// ---------------------------------------------------------------------------
#define AQT   128
#define AKT   64
#define AROWW 36                        // smem words per row (72 bf16)
#define AROWB 144
#define KTILE_B (64 * AROWB)            // 9216 B
#define ASTAGE_B (4 * KTILE_B)          // Kh,Kl,Vh,Vl
#define ATTN_SMEM (2 * ASTAGE_B)        // 73728 B

__global__ __launch_bounds__(256)
void attn_mma(__nv_bfloat16* __restrict__ Oh, __nv_bfloat16* __restrict__ Ol,
              const __nv_bfloat16* __restrict__ Qh, const __nv_bfloat16* __restrict__ Ql,
              const __nv_bfloat16* __restrict__ Kh, const __nv_bfloat16* __restrict__ Kl,
              const __nv_bfloat16* __restrict__ Vh, const __nv_bfloat16* __restrict__ Vl)
{
    const int tid  = threadIdx.x;
    const int wid  = tid >> 5;
    const int lane = tid & 31;
    const int g    = lane >> 2;
    const int t4   = lane & 3;
    const int qt   = blockIdx.x;
    const int h    = blockIdx.y;
    const int b    = blockIdx.z;
    const uint32_t sb = smem_u32(dsm);

    // ---- stage Q, load fragments to registers ----
    {
#pragma unroll
        for (int j = 0; j < 8; j++) {
            const int idx = tid + j * 256;           // 0..2047
            const int hs  = idx >> 10;
            const int rem = idx & 1023;
            const int row = rem >> 3;
            const int seg = rem & 7;
            const __nv_bfloat16* src = (hs ? Ql : Qh) +
                ((size_t)(b * NN + qt * AQT + row) * CDIM + h * DD + seg * 8);
            cp16(sb + hs * (128 * AROWB) + row * AROWB + seg * 16, src);
        }
        cp_commit(); cp_wait<0>(); __syncthreads();
    }
    uint32_t qfh[4][4], qfl[4][4];
    {
        const uint32_t* Q0 = (const uint32_t*)dsm;
        const uint32_t* Q1 = (const uint32_t*)(dsm + 128 * AROWB);
        const int r0 = (wid * 16 + g) * AROWW + t4;
        const int r1 = r0 + 8 * AROWW;
#pragma unroll
        for (int kf = 0; kf < 4; kf++) {
            qfh[kf][0] = Q0[r0 + 8 * kf];     qfh[kf][1] = Q1 == Q1 ? Q0[r1 + 8 * kf] : 0;
            qfh[kf][2] = Q0[r0 + 4 + 8 * kf]; qfh[kf][3] = Q0[r1 + 4 + 8 * kf];
            qfl[kf][0] = Q1[r0 + 8 * kf];     qfl[kf][1] = Q1[r1 + 8 * kf];
            qfl[kf][2] = Q1[r0 + 4 + 8 * kf]; qfl[kf][3] = Q1[r1 + 4 + 8 * kf];
        }
    }
    __syncthreads();    // smem now reused for K/V stages

    const size_t kbase = (size_t)b * LLEN * CDIM + h * DD;
    uint4 vreg[4];

    // K loads: 1024 x 16B segs (both halves), 4 per thread
#define ISSUE_K(cc, buf) do {                                                 \
        _Pragma("unroll")                                                     \
        for (int j = 0; j < 4; j++) {                                         \
            const int idx = tid + j * 256;                                    \
            const int hs  = idx >> 9;                                         \
            const int rem = idx & 511;                                        \
            const int row = rem >> 3;                                         \
            const int seg = rem & 7;                                          \
            const __nv_bfloat16* src = (hs ? Kl : Kh) + kbase +               \
                (size_t)((cc) * AKT + row) * CDIM + seg * 8;                  \
            cp16(sb + (buf) * ASTAGE_B + hs * KTILE_B + row * AROWB + seg * 16, src); \
        }                                                                     \
    } while (0)

#define LDG_V(cc) do {                                                        \
        _Pragma("unroll")                                                     \
        for (int j = 0; j < 4; j++) {                                         \
            const int idx = tid + j * 256;                                    \
            const int hs  = idx >> 9;                                         \
            const int rem = idx & 511;                                        \
            const int row = rem >> 3;                                         \
            const int seg = rem & 7;                                          \
            const __nv_bfloat16* src = (hs ? Vl : Vh) + kbase +               \
                (size_t)((cc) * AKT + row) * CDIM + seg * 8;                  \
            vreg[j] = *(const uint4*)src;                                     \
        }                                                                     \
    } while (0)

#define STS_V(buf) do {                                                       \
        _Pragma("unroll")                                                     \
        for (int j = 0; j < 4; j++) {                                         \
            const int idx = tid + j * 256;                                    \
            const int hs  = idx >> 9;                                         \
            const int rem = idx & 511;                                        \
            const int row = rem >> 3;                                         \
            const int seg = rem & 7;                                          \
            __nv_bfloat16* bp = (__nv_bfloat16*)(dsm + (buf) * ASTAGE_B +     \
                                 (2 + hs) * KTILE_B);                         \
            __nv_bfloat16 tv[8];                                              \
            *(uint4*)tv = vreg[j];                                            \
            _Pragma("unroll")                                                 \
            for (int e = 0; e < 8; e++)                                       \
                bp[(seg * 8 + e) * 72 + row] = tv[e];                         \
        }                                                                     \
    } while (0)

    float m0 = -1e30f, m1 = -1e30f, l0 = 0.0f, l1 = 0.0f;
    float o[8][4];
#pragma unroll
    for (int nf = 0; nf < 8; nf++)
#pragma unroll
        for (int j = 0; j < 4; j++) o[nf][j] = 0.0f;

    ISSUE_K(0, 0); cp_commit();
    LDG_V(0);
    cp_wait<0>(); STS_V(0); __syncthreads();

    const int NC = LLEN / AKT;
    for (int c = 0; c < NC; c++) {
        const int buf = c & 1;
        if (c + 1 < NC) { ISSUE_K(c + 1, buf ^ 1); cp_commit(); LDG_V(c + 1); }

        // ---- S = Q K^T (bf16x3, fp32 accum) ----
        float s[8][4];
#pragma unroll
        for (int nf = 0; nf < 8; nf++)
#pragma unroll
            for (int j = 0; j < 4; j++) s[nf][j] = 0.0f;

        {
            const uint32_t* pKh = (const uint32_t*)(dsm + buf * ASTAGE_B);
            const uint32_t* pKl = pKh + KTILE_B / 4;
#pragma unroll
            for (int kf = 0; kf < 4; kf++)
#pragma unroll
                for (int nf = 0; nf < 8; nf++) {
                    const int r = (nf * 8 + g) * AROWW + t4 + 8 * kf;
                    const uint32_t bh0 = pKh[r], bh1 = pKh[r + 4];
                    const uint32_t bl0 = pKl[r], bl1 = pKl[r + 4];
                    mma_bf16(s[nf], qfh[kf][0], qfh[kf][1], qfh[kf][2], qfh[kf][3], bh0, bh1);
                    mma_bf16(s[nf], qfh[kf][0], qfh[kf][1], qfh[kf][2], qfh[kf][3], bl0, bl1);
                    mma_bf16(s[nf], qfl[kf][0], qfl[kf][1], qfl[kf][2], qfl[kf][3], bh0, bh1);
                }
        }

        if (c + 1 < NC) STS_V(buf ^ 1);

        // ---- online softmax (warp-local; rows g and g+8) ----
        float cm0 = -1e30f, cm1 = -1e30f;
#pragma unroll
        for (int nf = 0; nf < 8; nf++) {
            cm0 = fmaxf(cm0, fmaxf(s[nf][0], s[nf][1]));
            cm1 = fmaxf(cm1, fmaxf(s[nf][2], s[nf][3]));
        }
        cm0 = fmaxf(cm0, __shfl_xor_sync(0xFFFFFFFFu, cm0, 1));
        cm0 = fmaxf(cm0, __shfl_xor_sync(0xFFFFFFFFu, cm0, 2));
        cm1 = fmaxf(cm1, __shfl_xor_sync(0xFFFFFFFFu, cm1, 1));
        cm1 = fmaxf(cm1, __shfl_xor_sync(0xFFFFFFFFu, cm1, 2));
        const float mn0 = fmaxf(m0, cm0 * ATTN_SCALE);
        const float mn1 = fmaxf(m1, cm1 * ATTN_SCALE);
        const float al0 = __expf(m0 - mn0);
        const float al1 = __expf(m1 - mn1);
        float sum0 = 0.0f, sum1 = 0.0f;
#pragma unroll
        for (int nf = 0; nf < 8; nf++) {
            s[nf][0] = __expf(s[nf][0] * ATTN_SCALE - mn0); sum0 += s[nf][0];
            s[nf][1] = __expf(s[nf][1] * ATTN_SCALE - mn0); sum0 += s[nf][1];
            s[nf][2] = __expf(s[nf][2] * ATTN_SCALE - mn1); sum1 += s[nf][2];
            s[nf][3] = __expf(s[nf][3] * ATTN_SCALE - mn1); sum1 += s[nf][3];
        }
        sum0 += __shfl_xor_sync(0xFFFFFFFFu, sum0, 1);
        sum0 += __shfl_xor_sync(0xFFFFFFFFu, sum0, 2);
        sum1 += __shfl_xor_sync(0xFFFFFFFFu, sum1, 1);
        sum1 += __shfl_xor_sync(0xFFFFFFFFu, sum1, 2);
        l0 = l0 * al0 + sum0; m0 = mn0;
        l1 = l1 * al1 + sum1; m1 = mn1;
#pragma unroll
        for (int nf = 0; nf < 8; nf++) {
            o[nf][0] *= al0; o[nf][1] *= al0;
            o[nf][2] *= al1; o[nf][3] *= al1;
        }

        // ---- O += P V (P split hi/lo in registers) ----
        {
            const uint32_t* pVh = (const uint32_t*)(dsm + buf * ASTAGE_B + 2 * KTILE_B);
            const uint32_t* pVl = pVh + KTILE_B / 4;
#pragma unroll
            for (int kf = 0; kf < 4; kf++) {
                uint32_t ph[4], pl[4];
                pack_hl(s[2 * kf][0],     s[2 * kf][1],     ph[0], pl[0]);
                pack_hl(s[2 * kf][2],     s[2 * kf][3],     ph[1], pl[1]);
                pack_hl(s[2 * kf + 1][0], s[2 * kf + 1][1], ph[2], pl[2]);
                pack_hl(s[2 * kf + 1][2], s[2 * kf + 1][3], ph[3], pl[3]);
#pragma unroll
                for (int nf = 0; nf < 8; nf++) {
                    const int r = (nf * 8 + g) * AROWW + t4 + 8 * kf;
                    const uint32_t vh0 = pVh[r], vh1 = pVh[r + 4];
                    const uint32_t vl0 = pVl[r], vl1 = pVl[r + 4];
                    mma_bf16(o[nf], ph[0], ph[1], ph[2], ph[3], vh0, vh1);
                    mma_bf16(o[nf], ph[0], ph[1], ph[2], ph[3], vl0, vl1);
                    mma_bf16(o[nf], pl[0], pl[1], pl[2], pl[3], vh0, vh1);
                }
            }
        }

        if (c + 1 < NC) cp_wait<0>();
        __syncthreads();
    }

    // ---- normalize and write bf16 hi/lo ----
    const float inv0 = 1.0f / l0;
    const float inv1 = 1.0f / l1;
    const int row0 = qt * AQT + wid * 16 + g;
#pragma unroll
    for (int nf = 0; nf < 8; nf++) {
        const int col = h * DD + nf * 8 + 2 * t4;
        const size_t a0 = (size_t)(b * NN + row0) * CDIM + col;
        const size_t a1 = (size_t)(b * NN + row0 + 8) * CDIM + col;
        uint32_t h0, lo0, h1, lo1;
        pack_hl(o[nf][0] * inv0, o[nf][1] * inv0, h0, lo0);
        pack_hl(o[nf][2] * inv1, o[nf][3] * inv1, h1, lo1);
        *(uint32_t*)&Oh[a0] = h0; *(uint32_t*)&Ol[a0] = lo0;
        *(uint32_t*)&Oh[a1] = h1; *(uint32_t*)&Ol[a1] = lo1;
    }
#undef ISSUE_K
#undef LDG_V
#undef STS_V
}

// ---------------------------------------------------------------------------
// Launch
// ---------------------------------------------------------------------------
extern "C" void kernel_launch(void* const* d_in, const int* in_sizes, int n_in,
                              void* d_out, int out_size)
{
    const float* x  = (const float*)d_in[0];
    const float* y  = (const float*)d_in[1];
    const float* Wq = (const float*)d_in[2];
    const float* Wk = (const float*)d_in[3];
    const float* Wv = (const float*)d_in[4];
    const float* Wp = (const float*)d_in[5];
    const float* bp = (const float*)d_in[6];
    float* out = (float*)d_out;

    __nv_bfloat16 *xh, *xl, *yh, *yl, *wh, *wl;
    __nv_bfloat16 *qh, *ql, *kh, *kl, *vh, *vl, *aoh, *aol;
    cudaGetSymbolAddress((void**)&xh, g_xh);   cudaGetSymbolAddress((void**)&xl, g_xl);
    cudaGetSymbolAddress((void**)&yh, g_yh);   cudaGetSymbolAddress((void**)&yl, g_yl);
    cudaGetSymbolAddress((void**)&wh, g_wh);   cudaGetSymbolAddress((void**)&wl, g_wl);
    cudaGetSymbolAddress((void**)&qh, g_qh);   cudaGetSymbolAddress((void**)&ql, g_ql);
    cudaGetSymbolAddress((void**)&kh, g_kh);   cudaGetSymbolAddress((void**)&kl, g_kl);
    cudaGetSymbolAddress((void**)&vh, g_vh);   cudaGetSymbolAddress((void**)&vl, g_vl);
    cudaGetSymbolAddress((void**)&aoh, g_aoh); cudaGetSymbolAddress((void**)&aol, g_aol);

    cudaFuncSetAttribute(gemm_mma<true>,  cudaFuncAttributeMaxDynamicSharedMemorySize, GEMM_SMEM);
    cudaFuncSetAttribute(gemm_mma<false>, cudaFuncAttributeMaxDynamicSharedMemorySize, GEMM_SMEM);
    cudaFuncSetAttribute(attn_mma, cudaFuncAttributeMaxDynamicSharedMemorySize, ATTN_SMEM);

    const int M1 = BB * NN;     // 2048
    const int M2 = BB * LLEN;   // 8192
    const int WSZ = CDIM * CDIM;

    // Splits (fp32 -> bf16 hi/lo)
    {
        int n4;
        n4 = (M1 * CDIM) / 4;
        split_bf16<<<(n4 + 255) / 256, 256>>>(x, xh, xl, n4);
        n4 = (M2 * CDIM) / 4;
        split_bf16<<<(n4 + 255) / 256, 256>>>(y, yh, yl, n4);
        n4 = WSZ / 4;
        split_bf16<<<(n4 + 255) / 256, 256>>>(Wq, wh + 0 * WSZ, wl + 0 * WSZ, n4);
        split_bf16<<<(n4 + 255) / 256, 256>>>(Wk, wh + 1 * WSZ, wl + 1 * WSZ, n4);
        split_bf16<<<(n4 + 255) / 256, 256>>>(Wv, wh + 2 * WSZ, wl + 2 * WSZ, n4);
        split_bf16<<<(n4 + 255) / 256, 256>>>(Wp, wh + 3 * WSZ, wl + 3 * WSZ, n4);
    }

    // Projections -> bf16 hi/lo directly
    gemm_mma<false><<<dim3(CDIM / 128, M1 / 128), 256, GEMM_SMEM>>>(
        nullptr, qh, ql, xh, xl, wh + 0 * WSZ, wl + 0 * WSZ, nullptr, M1, CDIM, CDIM);
    gemm_mma<false><<<dim3(CDIM / 128, M2 / 128), 256, GEMM_SMEM>>>(
        nullptr, kh, kl, yh, yl, wh + 1 * WSZ, wl + 1 * WSZ, nullptr, M2, CDIM, CDIM);
    gemm_mma<false><<<dim3(CDIM / 128, M2 / 128), 256, GEMM_SMEM>>>(
        nullptr, vh, vl, yh, yl, wh + 2 * WSZ, wl + 2 * WSZ, nullptr, M2, CDIM, CDIM);

    // Flash attention on tensor cores -> bf16 hi/lo
    attn_mma<<<dim3(NN / AQT, HH, BB), 256, ATTN_SMEM>>>(
        aoh, aol, qh, ql, kh, kl, vh, vl);

    // Output projection (fp32 + bias)
    gemm_mma<true><<<dim3(CDIM / 128, M1 / 128), 256, GEMM_SMEM>>>(
        out, nullptr, nullptr, aoh, aol, wh + 3 * WSZ, wl + 3 * WSZ, bp, M1, CDIM, CDIM);
}

// round 7
// speedup vs baseline: 2.6132x; 1.1245x over previous
#include <cuda_runtime.h>
#include <cuda_bf16.h>
#include <math.h>
#include <stdint.h>

// Problem shape (fixed by the dataset)
#define BB   2
#define NN   1024
#define LLEN 4096
#define CDIM 1024
#define HH   16
#define DD   64

// ---------------- scratch (device globals; no allocs allowed) ---------------
__device__ __nv_bfloat16 g_xh[BB * NN * CDIM],   g_xl[BB * NN * CDIM];
__device__ __nv_bfloat16 g_yh[BB * LLEN * CDIM], g_yl[BB * LLEN * CDIM];
__device__ __nv_bfloat16 g_wh[4 * CDIM * CDIM],  g_wl[4 * CDIM * CDIM];
__device__ __nv_bfloat16 g_qh[BB * NN * CDIM],   g_ql[BB * NN * CDIM];   // pre-scaled by 0.125
__device__ __nv_bfloat16 g_kh[BB * LLEN * CDIM], g_kl[BB * LLEN * CDIM];
__device__ __nv_bfloat16 g_vh[BB * LLEN * CDIM], g_vl[BB * LLEN * CDIM];
__device__ __nv_bfloat16 g_aoh[BB * NN * CDIM],  g_aol[BB * NN * CDIM];

extern __shared__ char dsm[];

// ---------------------------------------------------------------------------
// helpers
// ---------------------------------------------------------------------------
static __device__ __forceinline__ uint32_t smem_u32(const void* p) {
    uint32_t a;
    asm("{ .reg .u64 t; cvta.to.shared.u64 t, %1; cvt.u32.u64 %0, t; }"
        : "=r"(a) : "l"(p));
    return a;
}
static __device__ __forceinline__ void cp16(uint32_t dst, const void* src) {
    asm volatile("cp.async.cg.shared.global [%0], [%1], 16;"
                 :: "r"(dst), "l"(src));
}
static __device__ __forceinline__ void cp_commit() {
    asm volatile("cp.async.commit_group;" ::: "memory");
}
template <int N_>
static __device__ __forceinline__ void cp_wait() {
    asm volatile("cp.async.wait_group %0;" :: "n"(N_) : "memory");
}
static __device__ __forceinline__ void mma_bf16(
    float* c, uint32_t a0, uint32_t a1, uint32_t a2, uint32_t a3,
    uint32_t b0, uint32_t b1)
{
    asm volatile(
        "mma.sync.aligned.m16n8k16.row.col.f32.bf16.bf16.f32 "
        "{%0,%1,%2,%3}, {%4,%5,%6,%7}, {%8,%9}, {%0,%1,%2,%3};"
        : "+f"(c[0]), "+f"(c[1]), "+f"(c[2]), "+f"(c[3])
        : "r"(a0), "r"(a1), "r"(a2), "r"(a3), "r"(b0), "r"(b1));
}
static __device__ __forceinline__ void ldsm_x2(uint32_t& r0, uint32_t& r1, uint32_t addr) {
    asm volatile("ldmatrix.sync.aligned.m8n8.x2.shared.b16 {%0,%1}, [%2];"
                 : "=r"(r0), "=r"(r1) : "r"(addr));
}
static __device__ __forceinline__ void ldsm_x2_t(uint32_t& r0, uint32_t& r1, uint32_t addr) {
    asm volatile("ldmatrix.sync.aligned.m8n8.x2.trans.shared.b16 {%0,%1}, [%2];"
                 : "=r"(r0), "=r"(r1) : "r"(addr));
}
static __device__ __forceinline__ void pack_hl(
    float a, float b, uint32_t& hi, uint32_t& lo)
{
    __nv_bfloat162 h = __floats2bfloat162_rn(a, b);
    __nv_bfloat162 l = __floats2bfloat162_rn(a - __bfloat162float(h.x),
                                             b - __bfloat162float(h.y));
    hi = *(uint32_t*)&h;
    lo = *(uint32_t*)&l;
}

// ---------------------------------------------------------------------------
// split: fp32 -> bf16 hi + bf16 lo (residual)
// ---------------------------------------------------------------------------
__global__ void split_bf16(const float* __restrict__ src,
                           __nv_bfloat16* __restrict__ hi,
                           __nv_bfloat16* __restrict__ lo, int n4)
{
    int i = blockIdx.x * blockDim.x + threadIdx.x;
    if (i >= n4) return;
    float4 v = ((const float4*)src)[i];
    __nv_bfloat162 hh0 = __floats2bfloat162_rn(v.x, v.y);
    __nv_bfloat162 hh1 = __floats2bfloat162_rn(v.z, v.w);
    __nv_bfloat162 ll0 = __floats2bfloat162_rn(v.x - __bfloat162float(hh0.x),
                                               v.y - __bfloat162float(hh0.y));
    __nv_bfloat162 ll1 = __floats2bfloat162_rn(v.z - __bfloat162float(hh1.x),
                                               v.w - __bfloat162float(hh1.y));
    ((__nv_bfloat162*)hi)[i * 2 + 0] = hh0;
    ((__nv_bfloat162*)hi)[i * 2 + 1] = hh1;
    ((__nv_bfloat162*)lo)[i * 2 + 0] = ll0;
    ((__nv_bfloat162*)lo)[i * 2 + 1] = ll1;
}

// ---------------------------------------------------------------------------
// mma.sync GEMM (bf16x3 split): C[m][n] = sum_k A[m][k]*B[n][k] (+bias[n])
// CTA tile 128x128, BK=32, 256 threads (8 warps, 4m x 2n).
// OUTF32: fp32 C (+bias).  else: bf16 hi/lo outputs Ch, Cl, scaled by oscale.
// ---------------------------------------------------------------------------
#define ROWB   80
#define ROWW   20
#define TILEB  (128 * ROWB)
#define TILEW  (TILEB / 4)
#define STAGEB (4 * TILEB)
#define GEMM_SMEM (2 * STAGEB)         // 81920 B

template <bool OUTF32>
__global__ __launch_bounds__(256, 1)
void gemm_mma(float* __restrict__ C,
              __nv_bfloat16* __restrict__ Ch, __nv_bfloat16* __restrict__ Cl,
              const __nv_bfloat16* __restrict__ Ah, const __nv_bfloat16* __restrict__ Al,
              const __nv_bfloat16* __restrict__ Bh, const __nv_bfloat16* __restrict__ Bl,
              const float* __restrict__ bias, float oscale, int M, int N, int K)
{
    const int tid  = threadIdx.x;
    const int wid  = tid >> 5;
    const int lane = tid & 31;
    const int wm   = wid & 3;
    const int wn   = wid >> 2;
    const int g    = lane >> 2;
    const int t4   = lane & 3;
    const int m0   = blockIdx.y * 128;
    const int n0   = blockIdx.x * 128;

    const uint32_t sb = smem_u32(dsm);

    const int tsel = tid >> 6;
    const int lrow = tid & 63;
    const int segr = (tid >> 3) & 3;
    const __nv_bfloat16* gsrc =
        (tsel == 0) ? Ah : (tsel == 1) ? Al : (tsel == 2) ? Bh : Bl;
    const int trow0 = (tsel < 2) ? m0 : n0;
    const __nv_bfloat16* gp0 = gsrc + (size_t)(trow0 + lrow) * K;
    const __nv_bfloat16* gp1 = gp0 + (size_t)64 * K;
    const uint32_t sd0 = sb + tsel * TILEB + lrow * ROWB;
    const uint32_t sd1 = sd0 + 64 * ROWB;

    const int nchunk = K >> 5;

#define LOAD_STAGE(cc, buf) do {                                              \
        const uint32_t bo = (uint32_t)(buf) * STAGEB;                         \
        _Pragma("unroll")                                                     \
        for (int s = 0; s < 4; s++) {                                         \
            const int seg = (s + segr) & 3;                                   \
            cp16(sd0 + bo + seg * 16, gp0 + (cc) * 32 + seg * 8);             \
            cp16(sd1 + bo + seg * 16, gp1 + (cc) * 32 + seg * 8);             \
        }                                                                     \
    } while (0)

    float acc[2][8][4];
#pragma unroll
    for (int mf = 0; mf < 2; mf++)
#pragma unroll
        for (int nf = 0; nf < 8; nf++)
#pragma unroll
            for (int j = 0; j < 4; j++) acc[mf][nf][j] = 0.0f;

    LOAD_STAGE(0, 0);
    cp_commit();

    for (int c = 0; c < nchunk; c++) {
        const int buf = c & 1;
        if (c + 1 < nchunk) {
            LOAD_STAGE(c + 1, buf ^ 1);
            cp_commit();
            cp_wait<1>();
        } else {
            cp_wait<0>();
        }
        __syncthreads();

        const uint32_t* S   = (const uint32_t*)(dsm + buf * STAGEB);
        const uint32_t* pAh = S;
        const uint32_t* pAl = S + TILEW;
        const uint32_t* pBh = S + 2 * TILEW;
        const uint32_t* pBl = S + 3 * TILEW;

#pragma unroll
        for (int ks = 0; ks < 2; ks++) {
            const int kw = ks * 8;
            uint32_t ah[2][4], al[2][4], bh[8][2], bl[8][2];
#pragma unroll
            for (int mf = 0; mf < 2; mf++) {
                const int r = (wm * 32 + mf * 16 + g) * ROWW + t4 + kw;
                ah[mf][0] = pAh[r];
                ah[mf][1] = pAh[r + 8 * ROWW];
                ah[mf][2] = pAh[r + 4];
                ah[mf][3] = pAh[r + 8 * ROWW + 4];
                al[mf][0] = pAl[r];
                al[mf][1] = pAl[r + 8 * ROWW];
                al[mf][2] = pAl[r + 4];
                al[mf][3] = pAl[r + 8 * ROWW + 4];
            }
#pragma unroll
            for (int nf = 0; nf < 8; nf++) {
                const int r = (wn * 64 + nf * 8 + g) * ROWW + t4 + kw;
                bh[nf][0] = pBh[r];
                bh[nf][1] = pBh[r + 4];
                bl[nf][0] = pBl[r];
                bl[nf][1] = pBl[r + 4];
            }
#pragma unroll
            for (int mf = 0; mf < 2; mf++)
#pragma unroll
                for (int nf = 0; nf < 8; nf++) {
                    mma_bf16(acc[mf][nf], ah[mf][0], ah[mf][1], ah[mf][2], ah[mf][3],
                             bh[nf][0], bh[nf][1]);
                    mma_bf16(acc[mf][nf], ah[mf][0], ah[mf][1], ah[mf][2], ah[mf][3],
                             bl[nf][0], bl[nf][1]);
                    mma_bf16(acc[mf][nf], al[mf][0], al[mf][1], al[mf][2], al[mf][3],
                             bh[nf][0], bh[nf][1]);
                }
        }
        __syncthreads();
    }

#pragma unroll
    for (int mf = 0; mf < 2; mf++) {
        const int row = m0 + wm * 32 + mf * 16 + g;
#pragma unroll
        for (int nf = 0; nf < 8; nf++) {
            const int col = n0 + wn * 64 + nf * 8 + 2 * t4;
            if (OUTF32) {
                float b0 = 0.0f, b1 = 0.0f;
                if (bias) { b0 = bias[col]; b1 = bias[col + 1]; }
                float2 v0, v1;
                v0.x = acc[mf][nf][0] + b0; v0.y = acc[mf][nf][1] + b1;
                v1.x = acc[mf][nf][2] + b0; v1.y = acc[mf][nf][3] + b1;
                *(float2*)&C[(size_t)row * N + col]       = v0;
                *(float2*)&C[(size_t)(row + 8) * N + col] = v1;
            } else {
                uint32_t h0, l0, h1, l1;
                pack_hl(acc[mf][nf][0] * oscale, acc[mf][nf][1] * oscale, h0, l0);
                pack_hl(acc[mf][nf][2] * oscale, acc[mf][nf][3] * oscale, h1, l1);
                *(uint32_t*)&Ch[(size_t)row * N + col]       = h0;
                *(uint32_t*)&Cl[(size_t)row * N + col]       = l0;
                *(uint32_t*)&Ch[(size_t)(row + 8) * N + col] = h1;
                *(uint32_t*)&Cl[(size_t)(row + 8) * N + col] = l1;
            }
        }
    }
#undef LOAD_STAGE
}

// ---------------------------------------------------------------------------
// Flash attention on mma.sync (bf16x3).  CTA = 128 queries of one (b,h).
// 8 warps x 16 rows; warp-local online softmax.  KT=64 key chunks.
// K AND V both cp.async'd row-major; K frags via ldmatrix, V frags via
// ldmatrix.trans (no scalar transpose).  Q pre-scaled by 0.125.
// ---------------------------------------------------------------------------
#define AQT   128
#define AKT   64
#define AROWW 36                        // smem words per row (72 bf16)
#define AROWB 144
#define KTILE_B (64 * AROWB)            // 9216 B
#define ASTAGE_B (4 * KTILE_B)          // Kh,Kl,Vh,Vl
#define ATTN_SMEM (2 * ASTAGE_B)        // 73728 B

__global__ __launch_bounds__(256)
void attn_mma(__nv_bfloat16* __restrict__ Oh, __nv_bfloat16* __restrict__ Ol,
              const __nv_bfloat16* __restrict__ Qh, const __nv_bfloat16* __restrict__ Ql,
              const __nv_bfloat16* __restrict__ Kh, const __nv_bfloat16* __restrict__ Kl,
              const __nv_bfloat16* __restrict__ Vh, const __nv_bfloat16* __restrict__ Vl)
{
    const int tid  = threadIdx.x;
    const int wid  = tid >> 5;
    const int lane = tid & 31;
    const int g    = lane >> 2;
    const int t4   = lane & 3;
    const int la   = lane & 15;       // ldmatrix x2 lane mapping
    const int l8   = la & 7;
    const int lh   = la >> 3;
    const int qt   = blockIdx.x;
    const int h    = blockIdx.y;
    const int b    = blockIdx.z;
    const uint32_t sb = smem_u32(dsm);

    // ---- stage Q (hi/lo), read fragments into registers ----
    {
#pragma unroll
        for (int j = 0; j < 8; j++) {
            const int idx = tid + j * 256;           // 0..2047
            const int hs  = idx >> 10;
            const int rem = idx & 1023;
            const int row = rem >> 3;
            const int seg = rem & 7;
            const __nv_bfloat16* src = (hs ? Ql : Qh) +
                ((size_t)(b * NN + qt * AQT + row) * CDIM + h * DD + seg * 8);
            cp16(sb + hs * (128 * AROWB) + row * AROWB + seg * 16, src);
        }
        cp_commit(); cp_wait<0>(); __syncthreads();
    }
    uint32_t qfh[4][4], qfl[4][4];
    {
        const uint32_t* Q0 = (const uint32_t*)dsm;
        const uint32_t* Q1 = (const uint32_t*)(dsm + 128 * AROWB);
        const int r0 = (wid * 16 + g) * AROWW + t4;
        const int r1 = r0 + 8 * AROWW;
#pragma unroll
        for (int kf = 0; kf < 4; kf++) {
            qfh[kf][0] = Q0[r0 + 8 * kf];     qfh[kf][1] = Q0[r1 + 8 * kf];
            qfh[kf][2] = Q0[r0 + 4 + 8 * kf]; qfh[kf][3] = Q0[r1 + 4 + 8 * kf];
            qfl[kf][0] = Q1[r0 + 8 * kf];     qfl[kf][1] = Q1[r1 + 8 * kf];
            qfl[kf][2] = Q1[r0 + 4 + 8 * kf]; qfl[kf][3] = Q1[r1 + 4 + 8 * kf];
        }
    }
    __syncthreads();    // smem now reused for K/V stages

    const size_t kbase = (size_t)b * LLEN * CDIM + h * DD;

    // K/V loads: 4 tiles (Kh,Kl,Vh,Vl) x 64 rows x 8 segs = 2048; 8/thread
#define ISSUE_KV(cc, buf) do {                                                \
        _Pragma("unroll")                                                     \
        for (int j = 0; j < 8; j++) {                                         \
            const int idx  = tid + j * 256;                                   \
            const int tile = idx >> 9;                                        \
            const int rem  = idx & 511;                                       \
            const int row  = rem >> 3;                                        \
            const int seg  = rem & 7;                                         \
            const __nv_bfloat16* src =                                        \
                ((tile == 0) ? Kh : (tile == 1) ? Kl : (tile == 2) ? Vh : Vl) \
                + kbase + (size_t)((cc) * AKT + row) * CDIM + seg * 8;        \
            cp16(sb + (buf) * ASTAGE_B + tile * KTILE_B + row * AROWB + seg * 16, src); \
        }                                                                     \
    } while (0)

    // per-lane ldmatrix address components
    const uint32_t koff = (uint32_t)(l8 * AROWB + lh * 16);
    const uint32_t voff = (uint32_t)((lh * 8 + l8) * AROWB);

    float m0 = -1e30f, m1 = -1e30f, l0 = 0.0f, l1 = 0.0f;
    float o[8][4];
#pragma unroll
    for (int nf = 0; nf < 8; nf++)
#pragma unroll
        for (int j = 0; j < 4; j++) o[nf][j] = 0.0f;

    ISSUE_KV(0, 0); cp_commit();
    cp_wait<0>(); __syncthreads();

    const int NC = LLEN / AKT;
    for (int c = 0; c < NC; c++) {
        const int buf = c & 1;
        if (c + 1 < NC) { ISSUE_KV(c + 1, buf ^ 1); cp_commit(); }

        const uint32_t stg = sb + buf * ASTAGE_B;
        const uint32_t kbh = stg + koff;
        const uint32_t kbl = stg + KTILE_B + koff;
        const uint32_t vbh = stg + 2 * KTILE_B + voff;
        const uint32_t vbl = stg + 3 * KTILE_B + voff;

        // ---- S = Q K^T (bf16x3, fp32 accum; scale folded into Q) ----
        float s[8][4];
#pragma unroll
        for (int nf = 0; nf < 8; nf++)
#pragma unroll
            for (int j = 0; j < 4; j++) s[nf][j] = 0.0f;

#pragma unroll
        for (int kf = 0; kf < 4; kf++)
#pragma unroll
            for (int nf = 0; nf < 8; nf++) {
                uint32_t bh0, bh1, bl0, bl1;
                ldsm_x2(bh0, bh1, kbh + nf * (8 * AROWB) + kf * 32);
                ldsm_x2(bl0, bl1, kbl + nf * (8 * AROWB) + kf * 32);
                mma_bf16(s[nf], qfh[kf][0], qfh[kf][1], qfh[kf][2], qfh[kf][3], bh0, bh1);
                mma_bf16(s[nf], qfh[kf][0], qfh[kf][1], qfh[kf][2], qfh[kf][3], bl0, bl1);
                mma_bf16(s[nf], qfl[kf][0], qfl[kf][1], qfl[kf][2], qfl[kf][3], bh0, bh1);
            }

        // ---- online softmax (warp-local; rows g and g+8) ----
        float cm0 = -1e30f, cm1 = -1e30f;
#pragma unroll
        for (int nf = 0; nf < 8; nf++) {
            cm0 = fmaxf(cm0, fmaxf(s[nf][0], s[nf][1]));
            cm1 = fmaxf(cm1, fmaxf(s[nf][2], s[nf][3]));
        }
        cm0 = fmaxf(cm0, __shfl_xor_sync(0xFFFFFFFFu, cm0, 1));
        cm0 = fmaxf(cm0, __shfl_xor_sync(0xFFFFFFFFu, cm0, 2));
        cm1 = fmaxf(cm1, __shfl_xor_sync(0xFFFFFFFFu, cm1, 1));
        cm1 = fmaxf(cm1, __shfl_xor_sync(0xFFFFFFFFu, cm1, 2));
        const float mn0 = fmaxf(m0, cm0);
        const float mn1 = fmaxf(m1, cm1);
        const float al0 = __expf(m0 - mn0);
        const float al1 = __expf(m1 - mn1);
        float sum0 = 0.0f, sum1 = 0.0f;
#pragma unroll
        for (int nf = 0; nf < 8; nf++) {
            s[nf][0] = __expf(s[nf][0] - mn0); sum0 += s[nf][0];
            s[nf][1] = __expf(s[nf][1] - mn0); sum0 += s[nf][1];
            s[nf][2] = __expf(s[nf][2] - mn1); sum1 += s[nf][2];
            s[nf][3] = __expf(s[nf][3] - mn1); sum1 += s[nf][3];
        }
        sum0 += __shfl_xor_sync(0xFFFFFFFFu, sum0, 1);
        sum0 += __shfl_xor_sync(0xFFFFFFFFu, sum0, 2);
        sum1 += __shfl_xor_sync(0xFFFFFFFFu, sum1, 1);
        sum1 += __shfl_xor_sync(0xFFFFFFFFu, sum1, 2);
        l0 = l0 * al0 + sum0; m0 = mn0;
        l1 = l1 * al1 + sum1; m1 = mn1;
#pragma unroll
        for (int nf = 0; nf < 8; nf++) {
            o[nf][0] *= al0; o[nf][1] *= al0;
            o[nf][2] *= al1; o[nf][3] *= al1;
        }

        // ---- O += P V (P split hi/lo in registers; V frags via ldmatrix.trans)
#pragma unroll
        for (int kf = 0; kf < 4; kf++) {
            uint32_t ph[4], pl[4];
            pack_hl(s[2 * kf][0],     s[2 * kf][1],     ph[0], pl[0]);
            pack_hl(s[2 * kf][2],     s[2 * kf][3],     ph[1], pl[1]);
            pack_hl(s[2 * kf + 1][0], s[2 * kf + 1][1], ph[2], pl[2]);
            pack_hl(s[2 * kf + 1][2], s[2 * kf + 1][3], ph[3], pl[3]);
#pragma unroll
            for (int nf = 0; nf < 8; nf++) {
                uint32_t vh0, vh1, vl0, vl1;
                ldsm_x2_t(vh0, vh1, vbh + kf * (16 * AROWB) + nf * 16);
                ldsm_x2_t(vl0, vl1, vbl + kf * (16 * AROWB) + nf * 16);
                mma_bf16(o[nf], ph[0], ph[1], ph[2], ph[3], vh0, vh1);
                mma_bf16(o[nf], ph[0], ph[1], ph[2], ph[3], vl0, vl1);
                mma_bf16(o[nf], pl[0], pl[1], pl[2], pl[3], vh0, vh1);
            }
        }

        if (c + 1 < NC) cp_wait<0>();
        __syncthreads();
    }

    // ---- normalize and write bf16 hi/lo ----
    const float inv0 = 1.0f / l0;
    const float inv1 = 1.0f / l1;
    const int row0 = qt * AQT + wid * 16 + g;
#pragma unroll
    for (int nf = 0; nf < 8; nf++) {
        const int col = h * DD + nf * 8 + 2 * t4;
        const size_t a0 = (size_t)(b * NN + row0) * CDIM + col;
        const size_t a1 = (size_t)(b * NN + row0 + 8) * CDIM + col;
        uint32_t h0, lo0, h1, lo1;
        pack_hl(o[nf][0] * inv0, o[nf][1] * inv0, h0, lo0);
        pack_hl(o[nf][2] * inv1, o[nf][3] * inv1, h1, lo1);
        *(uint32_t*)&Oh[a0] = h0; *(uint32_t*)&Ol[a0] = lo0;
        *(uint32_t*)&Oh[a1] = h1; *(uint32_t*)&Ol[a1] = lo1;
    }
#undef ISSUE_KV
}

// ---------------------------------------------------------------------------
// Launch
// ---------------------------------------------------------------------------
extern "C" void kernel_launch(void* const* d_in, const int* in_sizes, int n_in,
                              void* d_out, int out_size)
{
    const float* x  = (const float*)d_in[0];
    const float* y  = (const float*)d_in[1];
    const float* Wq = (const float*)d_in[2];
    const float* Wk = (const float*)d_in[3];
    const float* Wv = (const float*)d_in[4];
    const float* Wp = (const float*)d_in[5];
    const float* bp = (const float*)d_in[6];
    float* out = (float*)d_out;

    __nv_bfloat16 *xh, *xl, *yh, *yl, *wh, *wl;
    __nv_bfloat16 *qh, *ql, *kh, *kl, *vh, *vl, *aoh, *aol;
    cudaGetSymbolAddress((void**)&xh, g_xh);   cudaGetSymbolAddress((void**)&xl, g_xl);
    cudaGetSymbolAddress((void**)&yh, g_yh);   cudaGetSymbolAddress((void**)&yl, g_yl);
    cudaGetSymbolAddress((void**)&wh, g_wh);   cudaGetSymbolAddress((void**)&wl, g_wl);
    cudaGetSymbolAddress((void**)&qh, g_qh);   cudaGetSymbolAddress((void**)&ql, g_ql);
    cudaGetSymbolAddress((void**)&kh, g_kh);   cudaGetSymbolAddress((void**)&kl, g_kl);
    cudaGetSymbolAddress((void**)&vh, g_vh);   cudaGetSymbolAddress((void**)&vl, g_vl);
    cudaGetSymbolAddress((void**)&aoh, g_aoh); cudaGetSymbolAddress((void**)&aol, g_aol);

    cudaFuncSetAttribute(gemm_mma<true>,  cudaFuncAttributeMaxDynamicSharedMemorySize, GEMM_SMEM);
    cudaFuncSetAttribute(gemm_mma<false>, cudaFuncAttributeMaxDynamicSharedMemorySize, GEMM_SMEM);
    cudaFuncSetAttribute(attn_mma, cudaFuncAttributeMaxDynamicSharedMemorySize, ATTN_SMEM);

    const int M1 = BB * NN;     // 2048
    const int M2 = BB * LLEN;   // 8192
    const int WSZ = CDIM * CDIM;

    // Splits (fp32 -> bf16 hi/lo)
    {
        int n4;
        n4 = (M1 * CDIM) / 4;
        split_bf16<<<(n4 + 255) / 256, 256>>>(x, xh, xl, n4);
        n4 = (M2 * CDIM) / 4;
        split_bf16<<<(n4 + 255) / 256, 256>>>(y, yh, yl, n4);
        n4 = WSZ / 4;
        split_bf16<<<(n4 + 255) / 256, 256>>>(Wq, wh + 0 * WSZ, wl + 0 * WSZ, n4);
        split_bf16<<<(n4 + 255) / 256, 256>>>(Wk, wh + 1 * WSZ, wl + 1 * WSZ, n4);
        split_bf16<<<(n4 + 255) / 256, 256>>>(Wv, wh + 2 * WSZ, wl + 2 * WSZ, n4);
        split_bf16<<<(n4 + 255) / 256, 256>>>(Wp, wh + 3 * WSZ, wl + 3 * WSZ, n4);
    }

    // Projections -> bf16 hi/lo directly (Q pre-scaled by 2^-3, exact)
    gemm_mma<false><<<dim3(CDIM / 128, M1 / 128), 256, GEMM_SMEM>>>(
        nullptr, qh, ql, xh, xl, wh + 0 * WSZ, wl + 0 * WSZ, nullptr, 0.125f, M1, CDIM, CDIM);
    gemm_mma<false><<<dim3(CDIM / 128, M2 / 128), 256, GEMM_SMEM>>>(
        nullptr, kh, kl, yh, yl, wh + 1 * WSZ, wl + 1 * WSZ, nullptr, 1.0f, M2, CDIM, CDIM);
    gemm_mma<false><<<dim3(CDIM / 128, M2 / 128), 256, GEMM_SMEM>>>(
        nullptr, vh, vl, yh, yl, wh + 2 * WSZ, wl + 2 * WSZ, nullptr, 1.0f, M2, CDIM, CDIM);

    // Flash attention on tensor cores -> bf16 hi/lo
    attn_mma<<<dim3(NN / AQT, HH, BB), 256, ATTN_SMEM>>>(
        aoh, aol, qh, ql, kh, kl, vh, vl);

    // Output projection (fp32 + bias)
    gemm_mma<true><<<dim3(CDIM / 128, M1 / 128), 256, GEMM_SMEM>>>(
        out, nullptr, nullptr, aoh, aol, wh + 3 * WSZ, wl + 3 * WSZ, bp, 1.0f, M1, CDIM, CDIM);
}

// round 8
// speedup vs baseline: 2.6824x; 1.0265x over previous
#include <cuda_runtime.h>
#include <cuda_bf16.h>
#include <math.h>
#include <stdint.h>

// Problem shape (fixed by the dataset)
#define BB   2
#define NN   1024
#define LLEN 4096
#define CDIM 1024
#define HH   16
#define DD   64

// ---------------- scratch (device globals; no allocs allowed) ---------------
__device__ __nv_bfloat16 g_xh[BB * NN * CDIM],   g_xl[BB * NN * CDIM];
__device__ __nv_bfloat16 g_yh[BB * LLEN * CDIM], g_yl[BB * LLEN * CDIM];
__device__ __nv_bfloat16 g_wh[4 * CDIM * CDIM],  g_wl[4 * CDIM * CDIM];
__device__ __nv_bfloat16 g_qh[BB * NN * CDIM],   g_ql[BB * NN * CDIM];   // pre-scaled by 0.125
__device__ __nv_bfloat16 g_kh[BB * LLEN * CDIM], g_kl[BB * LLEN * CDIM];
__device__ __nv_bfloat16 g_vh[BB * LLEN * CDIM], g_vl[BB * LLEN * CDIM];
__device__ __nv_bfloat16 g_aoh[BB * NN * CDIM],  g_aol[BB * NN * CDIM];

extern __shared__ char dsm[];

// ---------------------------------------------------------------------------
// helpers
// ---------------------------------------------------------------------------
static __device__ __forceinline__ uint32_t smem_u32(const void* p) {
    uint32_t a;
    asm("{ .reg .u64 t; cvta.to.shared.u64 t, %1; cvt.u32.u64 %0, t; }"
        : "=r"(a) : "l"(p));
    return a;
}
static __device__ __forceinline__ void cp16(uint32_t dst, const void* src) {
    asm volatile("cp.async.cg.shared.global [%0], [%1], 16;"
                 :: "r"(dst), "l"(src));
}
static __device__ __forceinline__ void cp_commit() {
    asm volatile("cp.async.commit_group;" ::: "memory");
}
template <int N_>
static __device__ __forceinline__ void cp_wait() {
    asm volatile("cp.async.wait_group %0;" :: "n"(N_) : "memory");
}
static __device__ __forceinline__ void mma_bf16(
    float* c, uint32_t a0, uint32_t a1, uint32_t a2, uint32_t a3,
    uint32_t b0, uint32_t b1)
{
    asm volatile(
        "mma.sync.aligned.m16n8k16.row.col.f32.bf16.bf16.f32 "
        "{%0,%1,%2,%3}, {%4,%5,%6,%7}, {%8,%9}, {%0,%1,%2,%3};"
        : "+f"(c[0]), "+f"(c[1]), "+f"(c[2]), "+f"(c[3])
        : "r"(a0), "r"(a1), "r"(a2), "r"(a3), "r"(b0), "r"(b1));
}
static __device__ __forceinline__ void ldsm_x4(uint32_t* r, uint32_t addr) {
    asm volatile("ldmatrix.sync.aligned.m8n8.x4.shared.b16 {%0,%1,%2,%3}, [%4];"
                 : "=r"(r[0]), "=r"(r[1]), "=r"(r[2]), "=r"(r[3]) : "r"(addr));
}
static __device__ __forceinline__ void ldsm_x2_t(uint32_t& r0, uint32_t& r1, uint32_t addr) {
    asm volatile("ldmatrix.sync.aligned.m8n8.x2.trans.shared.b16 {%0,%1}, [%2];"
                 : "=r"(r0), "=r"(r1) : "r"(addr));
}
static __device__ __forceinline__ void pack_hl(
    float a, float b, uint32_t& hi, uint32_t& lo)
{
    __nv_bfloat162 h = __floats2bfloat162_rn(a, b);
    __nv_bfloat162 l = __floats2bfloat162_rn(a - __bfloat162float(h.x),
                                             b - __bfloat162float(h.y));
    hi = *(uint32_t*)&h;
    lo = *(uint32_t*)&l;
}

// ---------------------------------------------------------------------------
// split: fp32 -> bf16 hi + bf16 lo (residual)
// ---------------------------------------------------------------------------
__global__ void split_bf16(const float* __restrict__ src,
                           __nv_bfloat16* __restrict__ hi,
                           __nv_bfloat16* __restrict__ lo, int n4)
{
    int i = blockIdx.x * blockDim.x + threadIdx.x;
    if (i >= n4) return;
    float4 v = ((const float4*)src)[i];
    __nv_bfloat162 hh0 = __floats2bfloat162_rn(v.x, v.y);
    __nv_bfloat162 hh1 = __floats2bfloat162_rn(v.z, v.w);
    __nv_bfloat162 ll0 = __floats2bfloat162_rn(v.x - __bfloat162float(hh0.x),
                                               v.y - __bfloat162float(hh0.y));
    __nv_bfloat162 ll1 = __floats2bfloat162_rn(v.z - __bfloat162float(hh1.x),
                                               v.w - __bfloat162float(hh1.y));
    ((__nv_bfloat162*)hi)[i * 2 + 0] = hh0;
    ((__nv_bfloat162*)hi)[i * 2 + 1] = hh1;
    ((__nv_bfloat162*)lo)[i * 2 + 0] = ll0;
    ((__nv_bfloat162*)lo)[i * 2 + 1] = ll1;
}

// ---------------------------------------------------------------------------
// mma.sync GEMM (bf16x3 split): C[m][n] = sum_k A[m][k]*B[n][k] (+bias[n])
// CTA tile 128x128, BK=32, 256 threads (8 warps, 4m x 2n).
// Fragments via ldmatrix x4; 2 CTAs/SM.
// ---------------------------------------------------------------------------
#define ROWB   80
#define ROWW   20
#define TILEB  (128 * ROWB)
#define STAGEB (4 * TILEB)
#define GEMM_SMEM (2 * STAGEB)         // 81920 B

template <bool OUTF32>
__global__ __launch_bounds__(256, 2)
void gemm_mma(float* __restrict__ C,
              __nv_bfloat16* __restrict__ Ch, __nv_bfloat16* __restrict__ Cl,
              const __nv_bfloat16* __restrict__ Ah, const __nv_bfloat16* __restrict__ Al,
              const __nv_bfloat16* __restrict__ Bh, const __nv_bfloat16* __restrict__ Bl,
              const float* __restrict__ bias, float oscale, int M, int N, int K)
{
    const int tid  = threadIdx.x;
    const int wid  = tid >> 5;
    const int lane = tid & 31;
    const int wm   = wid & 3;
    const int wn   = wid >> 2;
    const int g    = lane >> 2;
    const int t4   = lane & 3;
    const int m0   = blockIdx.y * 128;
    const int n0   = blockIdx.x * 128;

    const uint32_t sb = smem_u32(dsm);

    const int tsel = tid >> 6;
    const int lrow = tid & 63;
    const int segr = (tid >> 3) & 3;
    const __nv_bfloat16* gsrc =
        (tsel == 0) ? Ah : (tsel == 1) ? Al : (tsel == 2) ? Bh : Bl;
    const int trow0 = (tsel < 2) ? m0 : n0;
    const __nv_bfloat16* gp0 = gsrc + (size_t)(trow0 + lrow) * K;
    const __nv_bfloat16* gp1 = gp0 + (size_t)64 * K;
    const uint32_t sd0 = sb + tsel * TILEB + lrow * ROWB;
    const uint32_t sd1 = sd0 + 64 * ROWB;

    // per-lane ldmatrix address components (row = lane&15, 16B-unit = lane>>4)
    const uint32_t lmrow = (uint32_t)(lane & 15) * ROWB + (uint32_t)(lane >> 4) * 16;
    const uint32_t aoff  = (uint32_t)(wm * 32) * ROWB + lmrow;   // + mf*16*ROWB + ks*32
    const uint32_t boff  = (uint32_t)(wn * 64) * ROWB + lmrow;   // + nfp*16*ROWB + ks*32

    const int nchunk = K >> 5;

#define LOAD_STAGE(cc, buf) do {                                              \
        const uint32_t bo = (uint32_t)(buf) * STAGEB;                         \
        _Pragma("unroll")                                                     \
        for (int s = 0; s < 4; s++) {                                         \
            const int seg = (s + segr) & 3;                                   \
            cp16(sd0 + bo + seg * 16, gp0 + (cc) * 32 + seg * 8);             \
            cp16(sd1 + bo + seg * 16, gp1 + (cc) * 32 + seg * 8);             \
        }                                                                     \
    } while (0)

    float acc[2][8][4];
#pragma unroll
    for (int mf = 0; mf < 2; mf++)
#pragma unroll
        for (int nf = 0; nf < 8; nf++)
#pragma unroll
            for (int j = 0; j < 4; j++) acc[mf][nf][j] = 0.0f;

    LOAD_STAGE(0, 0);
    cp_commit();

    for (int c = 0; c < nchunk; c++) {
        const int buf = c & 1;
        if (c + 1 < nchunk) {
            LOAD_STAGE(c + 1, buf ^ 1);
            cp_commit();
            cp_wait<1>();
        } else {
            cp_wait<0>();
        }
        __syncthreads();

        const uint32_t stg = sb + buf * STAGEB;
        const uint32_t pAh = stg + aoff;
        const uint32_t pAl = stg + TILEB + aoff;
        const uint32_t pBh = stg + 2 * TILEB + boff;
        const uint32_t pBl = stg + 3 * TILEB + boff;

#pragma unroll
        for (int ks = 0; ks < 2; ks++) {
            const uint32_t kb = (uint32_t)(ks * 32);
            uint32_t ah[2][4], al[2][4];
#pragma unroll
            for (int mf = 0; mf < 2; mf++) {
                ldsm_x4(ah[mf], pAh + mf * (16 * ROWB) + kb);
                ldsm_x4(al[mf], pAl + mf * (16 * ROWB) + kb);
            }
#pragma unroll
            for (int nfp = 0; nfp < 4; nfp++) {
                uint32_t bh4[4], bl4[4];
                ldsm_x4(bh4, pBh + nfp * (16 * ROWB) + kb);
                ldsm_x4(bl4, pBl + nfp * (16 * ROWB) + kb);
                // nf even = (r0, r2), nf odd = (r1, r3)
#pragma unroll
                for (int mf = 0; mf < 2; mf++) {
                    float* c0 = acc[mf][2 * nfp];
                    float* c1 = acc[mf][2 * nfp + 1];
                    mma_bf16(c0, ah[mf][0], ah[mf][1], ah[mf][2], ah[mf][3], bh4[0], bh4[2]);
                    mma_bf16(c0, ah[mf][0], ah[mf][1], ah[mf][2], ah[mf][3], bl4[0], bl4[2]);
                    mma_bf16(c0, al[mf][0], al[mf][1], al[mf][2], al[mf][3], bh4[0], bh4[2]);
                    mma_bf16(c1, ah[mf][0], ah[mf][1], ah[mf][2], ah[mf][3], bh4[1], bh4[3]);
                    mma_bf16(c1, ah[mf][0], ah[mf][1], ah[mf][2], ah[mf][3], bl4[1], bl4[3]);
                    mma_bf16(c1, al[mf][0], al[mf][1], al[mf][2], al[mf][3], bh4[1], bh4[3]);
                }
            }
        }
        __syncthreads();
    }

#pragma unroll
    for (int mf = 0; mf < 2; mf++) {
        const int row = m0 + wm * 32 + mf * 16 + g;
#pragma unroll
        for (int nf = 0; nf < 8; nf++) {
            const int col = n0 + wn * 64 + nf * 8 + 2 * t4;
            if (OUTF32) {
                float b0 = 0.0f, b1 = 0.0f;
                if (bias) { b0 = bias[col]; b1 = bias[col + 1]; }
                float2 v0, v1;
                v0.x = acc[mf][nf][0] + b0; v0.y = acc[mf][nf][1] + b1;
                v1.x = acc[mf][nf][2] + b0; v1.y = acc[mf][nf][3] + b1;
                *(float2*)&C[(size_t)row * N + col]       = v0;
                *(float2*)&C[(size_t)(row + 8) * N + col] = v1;
            } else {
                uint32_t h0, l0, h1, l1;
                pack_hl(acc[mf][nf][0] * oscale, acc[mf][nf][1] * oscale, h0, l0);
                pack_hl(acc[mf][nf][2] * oscale, acc[mf][nf][3] * oscale, h1, l1);
                *(uint32_t*)&Ch[(size_t)row * N + col]       = h0;
                *(uint32_t*)&Cl[(size_t)row * N + col]       = l0;
                *(uint32_t*)&Ch[(size_t)(row + 8) * N + col] = h1;
                *(uint32_t*)&Cl[(size_t)(row + 8) * N + col] = l1;
            }
        }
    }
#undef LOAD_STAGE
}

// ---------------------------------------------------------------------------
// Flash attention on mma.sync (bf16x3).  CTA = 128 queries of one (b,h).
// 8 warps x 16 rows; warp-local online softmax.  KT=64 key chunks.
// Q persistent in smem (fragments re-read per chunk via ldmatrix x4);
// K frags ldmatrix x4, V frags ldmatrix.trans x2.  2 CTAs/SM, 1 wave.
// ---------------------------------------------------------------------------
#define AQT   128
#define AKT   64
#define AROWW 36
#define AROWB 144
#define QTILE_B (128 * AROWB)           // 18432 B per Q half
#define QSM_B   (2 * QTILE_B)           // 36864 B
#define KTILE_B (64 * AROWB)            // 9216 B
#define ASTAGE_B (4 * KTILE_B)          // Kh,Kl,Vh,Vl
#define ATTN_SMEM (QSM_B + 2 * ASTAGE_B)   // 110592 B

__global__ __launch_bounds__(256, 2)
void attn_mma(__nv_bfloat16* __restrict__ Oh, __nv_bfloat16* __restrict__ Ol,
              const __nv_bfloat16* __restrict__ Qh, const __nv_bfloat16* __restrict__ Ql,
              const __nv_bfloat16* __restrict__ Kh, const __nv_bfloat16* __restrict__ Kl,
              const __nv_bfloat16* __restrict__ Vh, const __nv_bfloat16* __restrict__ Vl)
{
    const int tid  = threadIdx.x;
    const int wid  = tid >> 5;
    const int lane = tid & 31;
    const int g    = lane >> 2;
    const int t4   = lane & 3;
    const int la   = lane & 15;
    const int l8   = la & 7;
    const int lh   = la >> 3;
    const int qt   = blockIdx.x;
    const int h    = blockIdx.y;
    const int b    = blockIdx.z;
    const uint32_t sb = smem_u32(dsm);

    // ---- stage Q (hi/lo) into persistent smem ----
    {
#pragma unroll
        for (int j = 0; j < 8; j++) {
            const int idx = tid + j * 256;           // 0..2047
            const int hs  = idx >> 10;
            const int rem = idx & 1023;
            const int row = rem >> 3;
            const int seg = rem & 7;
            const __nv_bfloat16* src = (hs ? Ql : Qh) +
                ((size_t)(b * NN + qt * AQT + row) * CDIM + h * DD + seg * 8);
            cp16(sb + hs * QTILE_B + row * AROWB + seg * 16, src);
        }
        cp_commit();
    }

    const size_t kbase = (size_t)b * LLEN * CDIM + h * DD;

#define ISSUE_KV(cc, buf) do {                                                \
        _Pragma("unroll")                                                     \
        for (int j = 0; j < 8; j++) {                                         \
            const int idx  = tid + j * 256;                                   \
            const int tile = idx >> 9;                                        \
            const int rem  = idx & 511;                                       \
            const int row  = rem >> 3;                                        \
            const int seg  = rem & 7;                                         \
            const __nv_bfloat16* src =                                        \
                ((tile == 0) ? Kh : (tile == 1) ? Kl : (tile == 2) ? Vh : Vl) \
                + kbase + (size_t)((cc) * AKT + row) * CDIM + seg * 8;        \
            cp16(sb + QSM_B + (buf) * ASTAGE_B + tile * KTILE_B               \
                 + row * AROWB + seg * 16, src);                              \
        }                                                                     \
    } while (0)

    // ldmatrix address components
    const uint32_t lmrow = (uint32_t)la * AROWB + (uint32_t)(lane >> 4) * 16;
    const uint32_t qoff  = (uint32_t)(wid * 16) * AROWB + lmrow;   // + kf*32
    const uint32_t koff  = lmrow;                                   // + nfp*16*AROWB + kf*32
    const uint32_t voff  = (uint32_t)((lh * 8 + l8) * AROWB);

    float m0 = -1e30f, m1 = -1e30f, l0 = 0.0f, l1 = 0.0f;
    float o[8][4];
#pragma unroll
    for (int nf = 0; nf < 8; nf++)
#pragma unroll
        for (int j = 0; j < 4; j++) o[nf][j] = 0.0f;

    ISSUE_KV(0, 0); cp_commit();
    cp_wait<0>(); __syncthreads();

    const int NC = LLEN / AKT;
    for (int c = 0; c < NC; c++) {
        const int buf = c & 1;
        if (c + 1 < NC) { ISSUE_KV(c + 1, buf ^ 1); cp_commit(); }

        const uint32_t stg = sb + QSM_B + buf * ASTAGE_B;
        const uint32_t vbh = stg + 2 * KTILE_B + voff;
        const uint32_t vbl = stg + 3 * KTILE_B + voff;

        // ---- S = Q K^T (bf16x3; scale folded into Q) ----
        float s[8][4];
#pragma unroll
        for (int nf = 0; nf < 8; nf++)
#pragma unroll
            for (int j = 0; j < 4; j++) s[nf][j] = 0.0f;

#pragma unroll
        for (int kf = 0; kf < 4; kf++) {
            const uint32_t kb = (uint32_t)(kf * 32);
            uint32_t qh4[4], ql4[4];
            ldsm_x4(qh4, sb + qoff + kb);
            ldsm_x4(ql4, sb + QTILE_B + qoff + kb);
#pragma unroll
            for (int nfp = 0; nfp < 4; nfp++) {
                uint32_t kh4[4], kl4[4];
                ldsm_x4(kh4, stg + koff + nfp * (16 * AROWB) + kb);
                ldsm_x4(kl4, stg + KTILE_B + koff + nfp * (16 * AROWB) + kb);
                float* s0 = s[2 * nfp];
                float* s1 = s[2 * nfp + 1];
                mma_bf16(s0, qh4[0], qh4[1], qh4[2], qh4[3], kh4[0], kh4[2]);
                mma_bf16(s0, qh4[0], qh4[1], qh4[2], qh4[3], kl4[0], kl4[2]);
                mma_bf16(s0, ql4[0], ql4[1], ql4[2], ql4[3], kh4[0], kh4[2]);
                mma_bf16(s1, qh4[0], qh4[1], qh4[2], qh4[3], kh4[1], kh4[3]);
                mma_bf16(s1, qh4[0], qh4[1], qh4[2], qh4[3], kl4[1], kl4[3]);
                mma_bf16(s1, ql4[0], ql4[1], ql4[2], ql4[3], kh4[1], kh4[3]);
            }
        }

        // ---- online softmax (warp-local; rows g and g+8) ----
        float cm0 = -1e30f, cm1 = -1e30f;
#pragma unroll
        for (int nf = 0; nf < 8; nf++) {
            cm0 = fmaxf(cm0, fmaxf(s[nf][0], s[nf][1]));
            cm1 = fmaxf(cm1, fmaxf(s[nf][2], s[nf][3]));
        }
        cm0 = fmaxf(cm0, __shfl_xor_sync(0xFFFFFFFFu, cm0, 1));
        cm0 = fmaxf(cm0, __shfl_xor_sync(0xFFFFFFFFu, cm0, 2));
        cm1 = fmaxf(cm1, __shfl_xor_sync(0xFFFFFFFFu, cm1, 1));
        cm1 = fmaxf(cm1, __shfl_xor_sync(0xFFFFFFFFu, cm1, 2));
        const float mn0 = fmaxf(m0, cm0);
        const float mn1 = fmaxf(m1, cm1);
        const float al0 = __expf(m0 - mn0);
        const float al1 = __expf(m1 - mn1);
        float sum0 = 0.0f, sum1 = 0.0f;
#pragma unroll
        for (int nf = 0; nf < 8; nf++) {
            s[nf][0] = __expf(s[nf][0] - mn0); sum0 += s[nf][0];
            s[nf][1] = __expf(s[nf][1] - mn0); sum0 += s[nf][1];
            s[nf][2] = __expf(s[nf][2] - mn1); sum1 += s[nf][2];
            s[nf][3] = __expf(s[nf][3] - mn1); sum1 += s[nf][3];
        }
        sum0 += __shfl_xor_sync(0xFFFFFFFFu, sum0, 1);
        sum0 += __shfl_xor_sync(0xFFFFFFFFu, sum0, 2);
        sum1 += __shfl_xor_sync(0xFFFFFFFFu, sum1, 1);
        sum1 += __shfl_xor_sync(0xFFFFFFFFu, sum1, 2);
        l0 = l0 * al0 + sum0; m0 = mn0;
        l1 = l1 * al1 + sum1; m1 = mn1;
#pragma unroll
        for (int nf = 0; nf < 8; nf++) {
            o[nf][0] *= al0; o[nf][1] *= al0;
            o[nf][2] *= al1; o[nf][3] *= al1;
        }

        // ---- O += P V (P split hi/lo in registers; V frags via ldmatrix.trans)
#pragma unroll
        for (int kf = 0; kf < 4; kf++) {
            uint32_t ph[4], pl[4];
            pack_hl(s[2 * kf][0],     s[2 * kf][1],     ph[0], pl[0]);
            pack_hl(s[2 * kf][2],     s[2 * kf][3],     ph[1], pl[1]);
            pack_hl(s[2 * kf + 1][0], s[2 * kf + 1][1], ph[2], pl[2]);
            pack_hl(s[2 * kf + 1][2], s[2 * kf + 1][3], ph[3], pl[3]);
#pragma unroll
            for (int nf = 0; nf < 8; nf++) {
                uint32_t vh0, vh1, vl0, vl1;
                ldsm_x2_t(vh0, vh1, vbh + kf * (16 * AROWB) + nf * 16);
                ldsm_x2_t(vl0, vl1, vbl + kf * (16 * AROWB) + nf * 16);
                mma_bf16(o[nf], ph[0], ph[1], ph[2], ph[3], vh0, vh1);
                mma_bf16(o[nf], ph[0], ph[1], ph[2], ph[3], vl0, vl1);
                mma_bf16(o[nf], pl[0], pl[1], pl[2], pl[3], vh0, vh1);
            }
        }

        if (c + 1 < NC) cp_wait<0>();
        __syncthreads();
    }

    // ---- normalize and write bf16 hi/lo ----
    const float inv0 = 1.0f / l0;
    const float inv1 = 1.0f / l1;
    const int row0 = qt * AQT + wid * 16 + g;
#pragma unroll
    for (int nf = 0; nf < 8; nf++) {
        const int col = h * DD + nf * 8 + 2 * t4;
        const size_t a0 = (size_t)(b * NN + row0) * CDIM + col;
        const size_t a1 = (size_t)(b * NN + row0 + 8) * CDIM + col;
        uint32_t h0, lo0, h1, lo1;
        pack_hl(o[nf][0] * inv0, o[nf][1] * inv0, h0, lo0);
        pack_hl(o[nf][2] * inv1, o[nf][3] * inv1, h1, lo1);
        *(uint32_t*)&Oh[a0] = h0; *(uint32_t*)&Ol[a0] = lo0;
        *(uint32_t*)&Oh[a1] = h1; *(uint32_t*)&Ol[a1] = lo1;
    }
#undef ISSUE_KV
}

// ---------------------------------------------------------------------------
// Launch
// ---------------------------------------------------------------------------
extern "C" void kernel_launch(void* const* d_in, const int* in_sizes, int n_in,
                              void* d_out, int out_size)
{
    const float* x  = (const float*)d_in[0];
    const float* y  = (const float*)d_in[1];
    const float* Wq = (const float*)d_in[2];
    const float* Wk = (const float*)d_in[3];
    const float* Wv = (const float*)d_in[4];
    const float* Wp = (const float*)d_in[5];
    const float* bp = (const float*)d_in[6];
    float* out = (float*)d_out;

    __nv_bfloat16 *xh, *xl, *yh, *yl, *wh, *wl;
    __nv_bfloat16 *qh, *ql, *kh, *kl, *vh, *vl, *aoh, *aol;
    cudaGetSymbolAddress((void**)&xh, g_xh);   cudaGetSymbolAddress((void**)&xl, g_xl);
    cudaGetSymbolAddress((void**)&yh, g_yh);   cudaGetSymbolAddress((void**)&yl, g_yl);
    cudaGetSymbolAddress((void**)&wh, g_wh);   cudaGetSymbolAddress((void**)&wl, g_wl);
    cudaGetSymbolAddress((void**)&qh, g_qh);   cudaGetSymbolAddress((void**)&ql, g_ql);
    cudaGetSymbolAddress((void**)&kh, g_kh);   cudaGetSymbolAddress((void**)&kl, g_kl);
    cudaGetSymbolAddress((void**)&vh, g_vh);   cudaGetSymbolAddress((void**)&vl, g_vl);
    cudaGetSymbolAddress((void**)&aoh, g_aoh); cudaGetSymbolAddress((void**)&aol, g_aol);

    cudaFuncSetAttribute(gemm_mma<true>,  cudaFuncAttributeMaxDynamicSharedMemorySize, GEMM_SMEM);
    cudaFuncSetAttribute(gemm_mma<false>, cudaFuncAttributeMaxDynamicSharedMemorySize, GEMM_SMEM);
    cudaFuncSetAttribute(attn_mma, cudaFuncAttributeMaxDynamicSharedMemorySize, ATTN_SMEM);

    const int M1 = BB * NN;     // 2048
    const int M2 = BB * LLEN;   // 8192
    const int WSZ = CDIM * CDIM;

    // Splits (fp32 -> bf16 hi/lo)
    {
        int n4;
        n4 = (M1 * CDIM) / 4;
        split_bf16<<<(n4 + 255) / 256, 256>>>(x, xh, xl, n4);
        n4 = (M2 * CDIM) / 4;
        split_bf16<<<(n4 + 255) / 256, 256>>>(y, yh, yl, n4);
        n4 = WSZ / 4;
        split_bf16<<<(n4 + 255) / 256, 256>>>(Wq, wh + 0 * WSZ, wl + 0 * WSZ, n4);
        split_bf16<<<(n4 + 255) / 256, 256>>>(Wk, wh + 1 * WSZ, wl + 1 * WSZ, n4);
        split_bf16<<<(n4 + 255) / 256, 256>>>(Wv, wh + 2 * WSZ, wl + 2 * WSZ, n4);
        split_bf16<<<(n4 + 255) / 256, 256>>>(Wp, wh + 3 * WSZ, wl + 3 * WSZ, n4);
    }

    // Projections -> bf16 hi/lo directly (Q pre-scaled by 2^-3, exact)
    gemm_mma<false><<<dim3(CDIM / 128, M1 / 128), 256, GEMM_SMEM>>>(
        nullptr, qh, ql, xh, xl, wh + 0 * WSZ, wl + 0 * WSZ, nullptr, 0.125f, M1, CDIM, CDIM);
    gemm_mma<false><<<dim3(CDIM / 128, M2 / 128), 256, GEMM_SMEM>>>(
        nullptr, kh, kl, yh, yl, wh + 1 * WSZ, wl + 1 * WSZ, nullptr, 1.0f, M2, CDIM, CDIM);
    gemm_mma<false><<<dim3(CDIM / 128, M2 / 128), 256, GEMM_SMEM>>>(
        nullptr, vh, vl, yh, yl, wh + 2 * WSZ, wl + 2 * WSZ, nullptr, 1.0f, M2, CDIM, CDIM);

    // Flash attention on tensor cores -> bf16 hi/lo
    attn_mma<<<dim3(NN / AQT, HH, BB), 256, ATTN_SMEM>>>(
        aoh, aol, qh, ql, kh, kl, vh, vl);

    // Output projection (fp32 + bias)
    gemm_mma<true><<<dim3(CDIM / 128, M1 / 128), 256, GEMM_SMEM>>>(
        out, nullptr, nullptr, aoh, aol, wh + 3 * WSZ, wl + 3 * WSZ, bp, 1.0f, M1, CDIM, CDIM);
}

// round 9
// speedup vs baseline: 2.9136x; 1.0862x over previous
#include <cuda_runtime.h>
#include <cuda_bf16.h>
#include <math.h>
#include <stdint.h>

// Problem shape (fixed by the dataset)
#define BB   2
#define NN   1024
#define LLEN 4096
#define CDIM 1024
#define HH   16
#define DD   64

// ---------------- scratch (device globals; no allocs allowed) ---------------
__device__ __nv_bfloat16 g_xh[BB * NN * CDIM],   g_xl[BB * NN * CDIM];
__device__ __nv_bfloat16 g_yh[BB * LLEN * CDIM], g_yl[BB * LLEN * CDIM];
__device__ __nv_bfloat16 g_wh[4 * CDIM * CDIM],  g_wl[4 * CDIM * CDIM];
__device__ __nv_bfloat16 g_qh[BB * NN * CDIM],   g_ql[BB * NN * CDIM];   // pre-scaled by 0.125
__device__ __nv_bfloat16 g_kh[BB * LLEN * CDIM], g_kl[BB * LLEN * CDIM];
__device__ __nv_bfloat16 g_vh[BB * LLEN * CDIM], g_vl[BB * LLEN * CDIM];
__device__ __nv_bfloat16 g_aoh[BB * NN * CDIM],  g_aol[BB * NN * CDIM];

extern __shared__ char dsm[];

// ---------------------------------------------------------------------------
// helpers
// ---------------------------------------------------------------------------
static __device__ __forceinline__ uint32_t smem_u32(const void* p) {
    uint32_t a;
    asm("{ .reg .u64 t; cvta.to.shared.u64 t, %1; cvt.u32.u64 %0, t; }"
        : "=r"(a) : "l"(p));
    return a;
}
static __device__ __forceinline__ void cp16(uint32_t dst, const void* src) {
    asm volatile("cp.async.cg.shared.global [%0], [%1], 16;"
                 :: "r"(dst), "l"(src));
}
static __device__ __forceinline__ void cp_commit() {
    asm volatile("cp.async.commit_group;" ::: "memory");
}
template <int N_>
static __device__ __forceinline__ void cp_wait() {
    asm volatile("cp.async.wait_group %0;" :: "n"(N_) : "memory");
}
static __device__ __forceinline__ void mma_bf16(
    float* c, uint32_t a0, uint32_t a1, uint32_t a2, uint32_t a3,
    uint32_t b0, uint32_t b1)
{
    asm volatile(
        "mma.sync.aligned.m16n8k16.row.col.f32.bf16.bf16.f32 "
        "{%0,%1,%2,%3}, {%4,%5,%6,%7}, {%8,%9}, {%0,%1,%2,%3};"
        : "+f"(c[0]), "+f"(c[1]), "+f"(c[2]), "+f"(c[3])
        : "r"(a0), "r"(a1), "r"(a2), "r"(a3), "r"(b0), "r"(b1));
}
static __device__ __forceinline__ void ldsm_x4(uint32_t* r, uint32_t addr) {
    asm volatile("ldmatrix.sync.aligned.m8n8.x4.shared.b16 {%0,%1,%2,%3}, [%4];"
                 : "=r"(r[0]), "=r"(r[1]), "=r"(r[2]), "=r"(r[3]) : "r"(addr));
}
static __device__ __forceinline__ void ldsm_x2_t(uint32_t& r0, uint32_t& r1, uint32_t addr) {
    asm volatile("ldmatrix.sync.aligned.m8n8.x2.trans.shared.b16 {%0,%1}, [%2];"
                 : "=r"(r0), "=r"(r1) : "r"(addr));
}
static __device__ __forceinline__ void pack_hl(
    float a, float b, uint32_t& hi, uint32_t& lo)
{
    __nv_bfloat162 h = __floats2bfloat162_rn(a, b);
    __nv_bfloat162 l = __floats2bfloat162_rn(a - __bfloat162float(h.x),
                                             b - __bfloat162float(h.y));
    hi = *(uint32_t*)&h;
    lo = *(uint32_t*)&l;
}

// ---------------------------------------------------------------------------
// fused split: all six fp32 tensors -> bf16 hi/lo in ONE launch
// ---------------------------------------------------------------------------
#define X4 ((BB * NN * CDIM) / 4)
#define Y4 ((BB * LLEN * CDIM) / 4)
#define W4 ((CDIM * CDIM) / 4)
#define TOT4 (X4 + Y4 + 4 * W4)

__global__ void split_all(const float* __restrict__ x, const float* __restrict__ y,
                          const float* __restrict__ Wq, const float* __restrict__ Wk,
                          const float* __restrict__ Wv, const float* __restrict__ Wp,
                          __nv_bfloat16* __restrict__ xh, __nv_bfloat16* __restrict__ xl,
                          __nv_bfloat16* __restrict__ yh, __nv_bfloat16* __restrict__ yl,
                          __nv_bfloat16* __restrict__ wh, __nv_bfloat16* __restrict__ wl)
{
    const int i = blockIdx.x * blockDim.x + threadIdx.x;
    if (i >= TOT4) return;
    const float* src; __nv_bfloat16 *hi, *lo; int j;
    if (i < X4)                    { src = x;  hi = xh; lo = xl; j = i; }
    else if (i < X4 + Y4)          { src = y;  hi = yh; lo = yl; j = i - X4; }
    else if (i < X4 + Y4 + W4)     { src = Wq; hi = wh;                lo = wl;                j = i - X4 - Y4; }
    else if (i < X4 + Y4 + 2 * W4) { src = Wk; hi = wh + CDIM * CDIM;  lo = wl + CDIM * CDIM;  j = i - X4 - Y4 - W4; }
    else if (i < X4 + Y4 + 3 * W4) { src = Wv; hi = wh + 2 * CDIM * CDIM; lo = wl + 2 * CDIM * CDIM; j = i - X4 - Y4 - 2 * W4; }
    else                           { src = Wp; hi = wh + 3 * CDIM * CDIM; lo = wl + 3 * CDIM * CDIM; j = i - X4 - Y4 - 3 * W4; }

    float4 v = ((const float4*)src)[j];
    __nv_bfloat162 hh0 = __floats2bfloat162_rn(v.x, v.y);
    __nv_bfloat162 hh1 = __floats2bfloat162_rn(v.z, v.w);
    __nv_bfloat162 ll0 = __floats2bfloat162_rn(v.x - __bfloat162float(hh0.x),
                                               v.y - __bfloat162float(hh0.y));
    __nv_bfloat162 ll1 = __floats2bfloat162_rn(v.z - __bfloat162float(hh1.x),
                                               v.w - __bfloat162float(hh1.y));
    ((__nv_bfloat162*)hi)[j * 2 + 0] = hh0;
    ((__nv_bfloat162*)hi)[j * 2 + 1] = hh1;
    ((__nv_bfloat162*)lo)[j * 2 + 0] = ll0;
    ((__nv_bfloat162*)lo)[j * 2 + 1] = ll1;
}

// ---------------------------------------------------------------------------
// GEMM body (bf16x3 split): C[m][n] = sum_k A[m][k]*B[n][k] (+bias[n])
// CTA tile 128x128, BK=32, 256 threads (8 warps, 4m x 2n), ldmatrix x4.
// ---------------------------------------------------------------------------
#define ROWB   80
#define TILEB  (128 * ROWB)
#define STAGEB (4 * TILEB)
#define GEMM_SMEM (2 * STAGEB)         // 81920 B

#define LOAD_STAGE(cc, buf) do {                                              \
        const uint32_t bo = (uint32_t)(buf) * STAGEB;                         \
        _Pragma("unroll")                                                     \
        for (int s = 0; s < 4; s++) {                                         \
            const int seg = (s + segr) & 3;                                   \
            cp16(sd0 + bo + seg * 16, gp0 + (cc) * 32 + seg * 8);             \
            cp16(sd1 + bo + seg * 16, gp1 + (cc) * 32 + seg * 8);             \
        }                                                                     \
    } while (0)

template <bool OUTF32>
static __device__ __forceinline__ void gemm_body(
    float* __restrict__ C,
    __nv_bfloat16* __restrict__ Ch, __nv_bfloat16* __restrict__ Cl,
    const __nv_bfloat16* __restrict__ Ah, const __nv_bfloat16* __restrict__ Al,
    const __nv_bfloat16* __restrict__ Bh, const __nv_bfloat16* __restrict__ Bl,
    const float* __restrict__ bias, float oscale, int N, int K, int bx, int by)
{
    const int tid  = threadIdx.x;
    const int wid  = tid >> 5;
    const int lane = tid & 31;
    const int wm   = wid & 3;
    const int wn   = wid >> 2;
    const int g    = lane >> 2;
    const int t4   = lane & 3;
    const int m0   = by * 128;
    const int n0   = bx * 128;

    const uint32_t sb = smem_u32(dsm);

    const int tsel = tid >> 6;
    const int lrow = tid & 63;
    const int segr = (tid >> 3) & 3;
    const __nv_bfloat16* gsrc =
        (tsel == 0) ? Ah : (tsel == 1) ? Al : (tsel == 2) ? Bh : Bl;
    const int trow0 = (tsel < 2) ? m0 : n0;
    const __nv_bfloat16* gp0 = gsrc + (size_t)(trow0 + lrow) * K;
    const __nv_bfloat16* gp1 = gp0 + (size_t)64 * K;
    const uint32_t sd0 = sb + tsel * TILEB + lrow * ROWB;
    const uint32_t sd1 = sd0 + 64 * ROWB;

    const uint32_t lmrow = (uint32_t)(lane & 15) * ROWB + (uint32_t)(lane >> 4) * 16;
    const uint32_t aoff  = (uint32_t)(wm * 32) * ROWB + lmrow;
    const uint32_t boff  = (uint32_t)(wn * 64) * ROWB + lmrow;

    const int nchunk = K >> 5;

    float acc[2][8][4];
#pragma unroll
    for (int mf = 0; mf < 2; mf++)
#pragma unroll
        for (int nf = 0; nf < 8; nf++)
#pragma unroll
            for (int j = 0; j < 4; j++) acc[mf][nf][j] = 0.0f;

    LOAD_STAGE(0, 0);
    cp_commit();

    for (int c = 0; c < nchunk; c++) {
        const int buf = c & 1;
        if (c + 1 < nchunk) {
            LOAD_STAGE(c + 1, buf ^ 1);
            cp_commit();
            cp_wait<1>();
        } else {
            cp_wait<0>();
        }
        __syncthreads();

        const uint32_t stg = sb + buf * STAGEB;
        const uint32_t pAh = stg + aoff;
        const uint32_t pAl = stg + TILEB + aoff;
        const uint32_t pBh = stg + 2 * TILEB + boff;
        const uint32_t pBl = stg + 3 * TILEB + boff;

#pragma unroll
        for (int ks = 0; ks < 2; ks++) {
            const uint32_t kb = (uint32_t)(ks * 32);
            uint32_t ah[2][4], al[2][4];
#pragma unroll
            for (int mf = 0; mf < 2; mf++) {
                ldsm_x4(ah[mf], pAh + mf * (16 * ROWB) + kb);
                ldsm_x4(al[mf], pAl + mf * (16 * ROWB) + kb);
            }
#pragma unroll
            for (int nfp = 0; nfp < 4; nfp++) {
                uint32_t bh4[4], bl4[4];
                ldsm_x4(bh4, pBh + nfp * (16 * ROWB) + kb);
                ldsm_x4(bl4, pBl + nfp * (16 * ROWB) + kb);
#pragma unroll
                for (int mf = 0; mf < 2; mf++) {
                    float* c0 = acc[mf][2 * nfp];
                    float* c1 = acc[mf][2 * nfp + 1];
                    mma_bf16(c0, ah[mf][0], ah[mf][1], ah[mf][2], ah[mf][3], bh4[0], bh4[2]);
                    mma_bf16(c0, ah[mf][0], ah[mf][1], ah[mf][2], ah[mf][3], bl4[0], bl4[2]);
                    mma_bf16(c0, al[mf][0], al[mf][1], al[mf][2], al[mf][3], bh4[0], bh4[2]);
                    mma_bf16(c1, ah[mf][0], ah[mf][1], ah[mf][2], ah[mf][3], bh4[1], bh4[3]);
                    mma_bf16(c1, ah[mf][0], ah[mf][1], ah[mf][2], ah[mf][3], bl4[1], bl4[3]);
                    mma_bf16(c1, al[mf][0], al[mf][1], al[mf][2], al[mf][3], bh4[1], bh4[3]);
                }
            }
        }
        __syncthreads();
    }

#pragma unroll
    for (int mf = 0; mf < 2; mf++) {
        const int row = m0 + wm * 32 + mf * 16 + g;
#pragma unroll
        for (int nf = 0; nf < 8; nf++) {
            const int col = n0 + wn * 64 + nf * 8 + 2 * t4;
            if (OUTF32) {
                float b0 = 0.0f, b1 = 0.0f;
                if (bias) { b0 = bias[col]; b1 = bias[col + 1]; }
                float2 v0, v1;
                v0.x = acc[mf][nf][0] + b0; v0.y = acc[mf][nf][1] + b1;
                v1.x = acc[mf][nf][2] + b0; v1.y = acc[mf][nf][3] + b1;
                *(float2*)&C[(size_t)row * N + col]       = v0;
                *(float2*)&C[(size_t)(row + 8) * N + col] = v1;
            } else {
                uint32_t h0, l0, h1, l1;
                pack_hl(acc[mf][nf][0] * oscale, acc[mf][nf][1] * oscale, h0, l0);
                pack_hl(acc[mf][nf][2] * oscale, acc[mf][nf][3] * oscale, h1, l1);
                *(uint32_t*)&Ch[(size_t)row * N + col]       = h0;
                *(uint32_t*)&Cl[(size_t)row * N + col]       = l0;
                *(uint32_t*)&Ch[(size_t)(row + 8) * N + col] = h1;
                *(uint32_t*)&Cl[(size_t)(row + 8) * N + col] = l1;
            }
        }
    }
}

// Fused Q/K/V projection: blockIdx.z selects the GEMM; Q (M=2048) early-exits
// its spare m-tiles.  One launch = 1152 working CTAs.
__global__ __launch_bounds__(256, 2)
void proj_fused(const __nv_bfloat16* __restrict__ xh, const __nv_bfloat16* __restrict__ xl,
                const __nv_bfloat16* __restrict__ yh, const __nv_bfloat16* __restrict__ yl,
                const __nv_bfloat16* __restrict__ wh, const __nv_bfloat16* __restrict__ wl,
                __nv_bfloat16* __restrict__ qh, __nv_bfloat16* __restrict__ ql,
                __nv_bfloat16* __restrict__ kh, __nv_bfloat16* __restrict__ kl,
                __nv_bfloat16* __restrict__ vh, __nv_bfloat16* __restrict__ vl)
{
    const int z = blockIdx.z;
    if (z == 0 && blockIdx.y >= (BB * NN) / 128) return;   // Q: only 16 m-tiles

    const __nv_bfloat16* Ah = (z == 0) ? xh : yh;
    const __nv_bfloat16* Al = (z == 0) ? xl : yl;
    const int wsel = z;                                    // Wq, Wk, Wv
    const __nv_bfloat16* Bh = wh + (size_t)wsel * CDIM * CDIM;
    const __nv_bfloat16* Bl = wl + (size_t)wsel * CDIM * CDIM;
    __nv_bfloat16* Ch = (z == 0) ? qh : (z == 1) ? kh : vh;
    __nv_bfloat16* Cl = (z == 0) ? ql : (z == 1) ? kl : vl;
    const float oscale = (z == 0) ? 0.125f : 1.0f;

    gemm_body<false>(nullptr, Ch, Cl, Ah, Al, Bh, Bl, nullptr, oscale,
                     CDIM, CDIM, blockIdx.x, blockIdx.y);
}

// Output projection (fp32 + bias)
__global__ __launch_bounds__(256, 2)
void gemm_out(float* __restrict__ C,
              const __nv_bfloat16* __restrict__ Ah, const __nv_bfloat16* __restrict__ Al,
              const __nv_bfloat16* __restrict__ Bh, const __nv_bfloat16* __restrict__ Bl,
              const float* __restrict__ bias)
{
    gemm_body<true>(C, nullptr, nullptr, Ah, Al, Bh, Bl, bias, 1.0f,
                    CDIM, CDIM, blockIdx.x, blockIdx.y);
}

// ---------------------------------------------------------------------------
// Flash attention on mma.sync (bf16x3) — unchanged from R7 (passing)
// ---------------------------------------------------------------------------
#define AQT   128
#define AKT   64
#define AROWB 144
#define QTILE_B (128 * AROWB)
#define QSM_B   (2 * QTILE_B)
#define KTILE_B (64 * AROWB)
#define ASTAGE_B (4 * KTILE_B)
#define ATTN_SMEM (QSM_B + 2 * ASTAGE_B)   // 110592 B

__global__ __launch_bounds__(256, 2)
void attn_mma(__nv_bfloat16* __restrict__ Oh, __nv_bfloat16* __restrict__ Ol,
              const __nv_bfloat16* __restrict__ Qh, const __nv_bfloat16* __restrict__ Ql,
              const __nv_bfloat16* __restrict__ Kh, const __nv_bfloat16* __restrict__ Kl,
              const __nv_bfloat16* __restrict__ Vh, const __nv_bfloat16* __restrict__ Vl)
{
    const int tid  = threadIdx.x;
    const int wid  = tid >> 5;
    const int lane = tid & 31;
    const int g    = lane >> 2;
    const int t4   = lane & 3;
    const int la   = lane & 15;
    const int l8   = la & 7;
    const int lh   = la >> 3;
    const int qt   = blockIdx.x;
    const int h    = blockIdx.y;
    const int b    = blockIdx.z;
    const uint32_t sb = smem_u32(dsm);

    {
#pragma unroll
        for (int j = 0; j < 8; j++) {
            const int idx = tid + j * 256;
            const int hs  = idx >> 10;
            const int rem = idx & 1023;
            const int row = rem >> 3;
            const int seg = rem & 7;
            const __nv_bfloat16* src = (hs ? Ql : Qh) +
                ((size_t)(b * NN + qt * AQT + row) * CDIM + h * DD + seg * 8);
            cp16(sb + hs * QTILE_B + row * AROWB + seg * 16, src);
        }
        cp_commit();
    }

    const size_t kbase = (size_t)b * LLEN * CDIM + h * DD;

#define ISSUE_KV(cc, buf) do {                                                \
        _Pragma("unroll")                                                     \
        for (int j = 0; j < 8; j++) {                                         \
            const int idx  = tid + j * 256;                                   \
            const int tile = idx >> 9;                                        \
            const int rem  = idx & 511;                                       \
            const int row  = rem >> 3;                                        \
            const int seg  = rem & 7;                                         \
            const __nv_bfloat16* src =                                        \
                ((tile == 0) ? Kh : (tile == 1) ? Kl : (tile == 2) ? Vh : Vl) \
                + kbase + (size_t)((cc) * AKT + row) * CDIM + seg * 8;        \
            cp16(sb + QSM_B + (buf) * ASTAGE_B + tile * KTILE_B               \
                 + row * AROWB + seg * 16, src);                              \
        }                                                                     \
    } while (0)

    const uint32_t lmrow = (uint32_t)la * AROWB + (uint32_t)(lane >> 4) * 16;
    const uint32_t qoff  = (uint32_t)(wid * 16) * AROWB + lmrow;
    const uint32_t koff  = lmrow;
    const uint32_t voff  = (uint32_t)((lh * 8 + l8) * AROWB);

    float m0 = -1e30f, m1 = -1e30f, l0 = 0.0f, l1 = 0.0f;
    float o[8][4];
#pragma unroll
    for (int nf = 0; nf < 8; nf++)
#pragma unroll
        for (int j = 0; j < 4; j++) o[nf][j] = 0.0f;

    ISSUE_KV(0, 0); cp_commit();
    cp_wait<0>(); __syncthreads();

    const int NC = LLEN / AKT;
    for (int c = 0; c < NC; c++) {
        const int buf = c & 1;
        if (c + 1 < NC) { ISSUE_KV(c + 1, buf ^ 1); cp_commit(); }

        const uint32_t stg = sb + QSM_B + buf * ASTAGE_B;
        const uint32_t vbh = stg + 2 * KTILE_B + voff;
        const uint32_t vbl = stg + 3 * KTILE_B + voff;

        float s[8][4];
#pragma unroll
        for (int nf = 0; nf < 8; nf++)
#pragma unroll
            for (int j = 0; j < 4; j++) s[nf][j] = 0.0f;

#pragma unroll
        for (int kf = 0; kf < 4; kf++) {
            const uint32_t kb = (uint32_t)(kf * 32);
            uint32_t qh4[4], ql4[4];
            ldsm_x4(qh4, sb + qoff + kb);
            ldsm_x4(ql4, sb + QTILE_B + qoff + kb);
#pragma unroll
            for (int nfp = 0; nfp < 4; nfp++) {
                uint32_t kh4[4], kl4[4];
                ldsm_x4(kh4, stg + koff + nfp * (16 * AROWB) + kb);
                ldsm_x4(kl4, stg + KTILE_B + koff + nfp * (16 * AROWB) + kb);
                float* s0 = s[2 * nfp];
                float* s1 = s[2 * nfp + 1];
                mma_bf16(s0, qh4[0], qh4[1], qh4[2], qh4[3], kh4[0], kh4[2]);
                mma_bf16(s0, qh4[0], qh4[1], qh4[2], qh4[3], kl4[0], kl4[2]);
                mma_bf16(s0, ql4[0], ql4[1], ql4[2], ql4[3], kh4[0], kh4[2]);
                mma_bf16(s1, qh4[0], qh4[1], qh4[2], qh4[3], kh4[1], kh4[3]);
                mma_bf16(s1, qh4[0], qh4[1], qh4[2], qh4[3], kl4[1], kl4[3]);
                mma_bf16(s1, ql4[0], ql4[1], ql4[2], ql4[3], kh4[1], kh4[3]);
            }
        }

        float cm0 = -1e30f, cm1 = -1e30f;
#pragma unroll
        for (int nf = 0; nf < 8; nf++) {
            cm0 = fmaxf(cm0, fmaxf(s[nf][0], s[nf][1]));
            cm1 = fmaxf(cm1, fmaxf(s[nf][2], s[nf][3]));
        }
        cm0 = fmaxf(cm0, __shfl_xor_sync(0xFFFFFFFFu, cm0, 1));
        cm0 = fmaxf(cm0, __shfl_xor_sync(0xFFFFFFFFu, cm0, 2));
        cm1 = fmaxf(cm1, __shfl_xor_sync(0xFFFFFFFFu, cm1, 1));
        cm1 = fmaxf(cm1, __shfl_xor_sync(0xFFFFFFFFu, cm1, 2));
        const float mn0 = fmaxf(m0, cm0);
        const float mn1 = fmaxf(m1, cm1);
        const float al0 = __expf(m0 - mn0);
        const float al1 = __expf(m1 - mn1);
        float sum0 = 0.0f, sum1 = 0.0f;
#pragma unroll
        for (int nf = 0; nf < 8; nf++) {
            s[nf][0] = __expf(s[nf][0] - mn0); sum0 += s[nf][0];
            s[nf][1] = __expf(s[nf][1] - mn0); sum0 += s[nf][1];
            s[nf][2] = __expf(s[nf][2] - mn1); sum1 += s[nf][2];
            s[nf][3] = __expf(s[nf][3] - mn1); sum1 += s[nf][3];
        }
        sum0 += __shfl_xor_sync(0xFFFFFFFFu, sum0, 1);
        sum0 += __shfl_xor_sync(0xFFFFFFFFu, sum0, 2);
        sum1 += __shfl_xor_sync(0xFFFFFFFFu, sum1, 1);
        sum1 += __shfl_xor_sync(0xFFFFFFFFu, sum1, 2);
        l0 = l0 * al0 + sum0; m0 = mn0;
        l1 = l1 * al1 + sum1; m1 = mn1;
#pragma unroll
        for (int nf = 0; nf < 8; nf++) {
            o[nf][0] *= al0; o[nf][1] *= al0;
            o[nf][2] *= al1; o[nf][3] *= al1;
        }

#pragma unroll
        for (int kf = 0; kf < 4; kf++) {
            uint32_t ph[4], pl[4];
            pack_hl(s[2 * kf][0],     s[2 * kf][1],     ph[0], pl[0]);
            pack_hl(s[2 * kf][2],     s[2 * kf][3],     ph[1], pl[1]);
            pack_hl(s[2 * kf + 1][0], s[2 * kf + 1][1], ph[2], pl[2]);
            pack_hl(s[2 * kf + 1][2], s[2 * kf + 1][3], ph[3], pl[3]);
#pragma unroll
            for (int nf = 0; nf < 8; nf++) {
                uint32_t vh0, vh1, vl0, vl1;
                ldsm_x2_t(vh0, vh1, vbh + kf * (16 * AROWB) + nf * 16);
                ldsm_x2_t(vl0, vl1, vbl + kf * (16 * AROWB) + nf * 16);
                mma_bf16(o[nf], ph[0], ph[1], ph[2], ph[3], vh0, vh1);
                mma_bf16(o[nf], ph[0], ph[1], ph[2], ph[3], vl0, vl1);
                mma_bf16(o[nf], pl[0], pl[1], pl[2], pl[3], vh0, vh1);
            }
        }

        if (c + 1 < NC) cp_wait<0>();
        __syncthreads();
    }

    const float inv0 = 1.0f / l0;
    const float inv1 = 1.0f / l1;
    const int row0 = qt * AQT + wid * 16 + g;
#pragma unroll
    for (int nf = 0; nf < 8; nf++) {
        const int col = h * DD + nf * 8 + 2 * t4;
        const size_t a0 = (size_t)(b * NN + row0) * CDIM + col;
        const size_t a1 = (size_t)(b * NN + row0 + 8) * CDIM + col;
        uint32_t h0, lo0, h1, lo1;
        pack_hl(o[nf][0] * inv0, o[nf][1] * inv0, h0, lo0);
        pack_hl(o[nf][2] * inv1, o[nf][3] * inv1, h1, lo1);
        *(uint32_t*)&Oh[a0] = h0; *(uint32_t*)&Ol[a0] = lo0;
        *(uint32_t*)&Oh[a1] = h1; *(uint32_t*)&Ol[a1] = lo1;
    }
#undef ISSUE_KV
}

// ---------------------------------------------------------------------------
// Launch
// ---------------------------------------------------------------------------
extern "C" void kernel_launch(void* const* d_in, const int* in_sizes, int n_in,
                              void* d_out, int out_size)
{
    const float* x  = (const float*)d_in[0];
    const float* y  = (const float*)d_in[1];
    const float* Wq = (const float*)d_in[2];
    const float* Wk = (const float*)d_in[3];
    const float* Wv = (const float*)d_in[4];
    const float* Wp = (const float*)d_in[5];
    const float* bp = (const float*)d_in[6];
    float* out = (float*)d_out;

    __nv_bfloat16 *xh, *xl, *yh, *yl, *wh, *wl;
    __nv_bfloat16 *qh, *ql, *kh, *kl, *vh, *vl, *aoh, *aol;
    cudaGetSymbolAddress((void**)&xh, g_xh);   cudaGetSymbolAddress((void**)&xl, g_xl);
    cudaGetSymbolAddress((void**)&yh, g_yh);   cudaGetSymbolAddress((void**)&yl, g_yl);
    cudaGetSymbolAddress((void**)&wh, g_wh);   cudaGetSymbolAddress((void**)&wl, g_wl);
    cudaGetSymbolAddress((void**)&qh, g_qh);   cudaGetSymbolAddress((void**)&ql, g_ql);
    cudaGetSymbolAddress((void**)&kh, g_kh);   cudaGetSymbolAddress((void**)&kl, g_kl);
    cudaGetSymbolAddress((void**)&vh, g_vh);   cudaGetSymbolAddress((void**)&vl, g_vl);
    cudaGetSymbolAddress((void**)&aoh, g_aoh); cudaGetSymbolAddress((void**)&aol, g_aol);

    cudaFuncSetAttribute(proj_fused, cudaFuncAttributeMaxDynamicSharedMemorySize, GEMM_SMEM);
    cudaFuncSetAttribute(gemm_out,   cudaFuncAttributeMaxDynamicSharedMemorySize, GEMM_SMEM);
    cudaFuncSetAttribute(attn_mma,   cudaFuncAttributeMaxDynamicSharedMemorySize, ATTN_SMEM);

    // 1. Fused splits (one launch)
    split_all<<<(TOT4 + 255) / 256, 256>>>(x, y, Wq, Wk, Wv, Wp,
                                           xh, xl, yh, yl, wh, wl);

    // 2. Fused Q/K/V projections (one launch; z = 0:Q, 1:K, 2:V)
    proj_fused<<<dim3(CDIM / 128, (BB * LLEN) / 128, 3), 256, GEMM_SMEM>>>(
        xh, xl, yh, yl, wh, wl, qh, ql, kh, kl, vh, vl);

    // 3. Flash attention on tensor cores -> bf16 hi/lo
    attn_mma<<<dim3(NN / AQT, HH, BB), 256, ATTN_SMEM>>>(
        aoh, aol, qh, ql, kh, kl, vh, vl);

    // 4. Output projection (fp32 + bias)
    gemm_out<<<dim3(CDIM / 128, (BB * NN) / 128), 256, GEMM_SMEM>>>(
        out, aoh, aol, wh + 3 * (size_t)CDIM * CDIM, wl + 3 * (size_t)CDIM * CDIM, bp);
}